// round 6
// baseline (speedup 1.0000x reference)
#include <cuda_runtime.h>

#define B    8
#define C    64
#define C3   192
#define Hdim 256
#define Wdim 256
#define HW   65536

// Scratch (device globals: allocation-free per harness rules)
__device__ float g_qkv[(size_t)B * C3 * HW];  // after 1x1 qkv conv (std NCHW)
__device__ float g_p  [(size_t)B * C3 * HW];  // after depthwise, patch-blocked:
                                              // [b*C3+ch][patchIdx(1024)][64]

// ---------------------------------------------------------------------------
// K1: 1x1 qkv GEMM. 64oc x 256px tile, 512 threads, 4oc x 8px per thread.
// grid (B*256, 3).
// ---------------------------------------------------------------------------
__global__ __launch_bounds__(512, 2) void k_qkv(const float* __restrict__ x,
                                                const float* __restrict__ w) {
    __shared__ float ws[64 * 64];    // 16 KB [oc][ic]
    __shared__ float xs[32 * 256];   // 32 KB [ic][px]
    int b   = blockIdx.x >> 8;
    int px0 = (blockIdx.x & 255) << 8;
    int ocH = blockIdx.y * 64;
    int t   = threadIdx.x;

    #pragma unroll
    for (int i = 0; i < 8; i++)
        ws[t + i * 512] = w[ocH * 64 + t + i * 512];

    int lane = t & 31;
    int pxA  = lane * 4;
    int oc0  = (t >> 5) * 4;       // 16 warps x 4 oc

    float acc[4][8];
    #pragma unroll
    for (int r = 0; r < 4; r++)
        #pragma unroll
        for (int j = 0; j < 8; j++) acc[r][j] = 0.f;

    const float* xb = x + (size_t)b * C * HW + px0;

    for (int ckk = 0; ckk < 2; ckk++) {
        __syncthreads();
        #pragma unroll
        for (int i = 0; i < 4; i++) {
            int idx = t + i * 512;           // 0..2047 float4s
            int ic  = idx >> 6;
            int p4  = idx & 63;
            *(float4*)(xs + ic * 256 + p4 * 4) =
                *(const float4*)(xb + (size_t)(ckk * 32 + ic) * HW + p4 * 4);
        }
        __syncthreads();

        #pragma unroll 4
        for (int ic = 0; ic < 32; ic++) {
            float4 a0 = *(const float4*)(xs + ic * 256 + pxA);
            float4 a1 = *(const float4*)(xs + ic * 256 + pxA + 128);
            float xv[8] = {a0.x, a0.y, a0.z, a0.w, a1.x, a1.y, a1.z, a1.w};
            int kk = ckk * 32 + ic;
            #pragma unroll
            for (int r = 0; r < 4; r++) {
                float wv = ws[(oc0 + r) * 64 + kk];
                #pragma unroll
                for (int j = 0; j < 8; j++) acc[r][j] += wv * xv[j];
            }
        }
    }

    float* ob = g_qkv + (size_t)b * C3 * HW + px0;
    #pragma unroll
    for (int r = 0; r < 4; r++) {
        float* dst = ob + (size_t)(ocH + oc0 + r) * HW;
        *(float4*)(dst + pxA) =
            make_float4(acc[r][0], acc[r][1], acc[r][2], acc[r][3]);
        *(float4*)(dst + pxA + 128) =
            make_float4(acc[r][4], acc[r][5], acc[r][6], acc[r][7]);
    }
}

// ---------------------------------------------------------------------------
// K2: 3x3 depthwise conv, 16x16 tile (4 patches), writes patch-blocked g_p.
// grid (16, 16, B*C3), 256 threads. Thread order patch-major so each warp's
// 32 stores are 128B contiguous within one patch block.
// ---------------------------------------------------------------------------
__global__ __launch_bounds__(256) void k_dw(const float* __restrict__ dw) {
    __shared__ float sx[18][24];     // halo 18x18, stride 24 (conflict-free)
    int plane = blockIdx.z;
    int ch    = plane % C3;
    int x0 = blockIdx.x * 16, y0 = blockIdx.y * 16;
    const float* ip = g_qkv + (size_t)plane * HW;
    int t = threadIdx.x;

    for (int i = t; i < 18 * 18; i += 256) {
        int ly = i / 18, lx = i - ly * 18;
        int gy = y0 + ly - 1, gx = x0 + lx - 1;
        float v = 0.f;
        if ((unsigned)gy < (unsigned)Hdim && (unsigned)gx < (unsigned)Wdim)
            v = ip[gy * Wdim + gx];
        sx[ly][lx] = v;
    }
    __syncthreads();

    int p  = t >> 6;                 // local patch 0..3
    int wi = t & 63;                 // within-patch index
    int py2 = p >> 1, px2 = p & 1;
    int wy = wi >> 3, wx = wi & 7;
    int ly = py2 * 8 + wy, lx = px2 * 8 + wx;

    const float* wp = dw + ch * 9;
    float acc = 0.f;
    #pragma unroll
    for (int dy = 0; dy < 3; dy++)
        #pragma unroll
        for (int dx = 0; dx < 3; dx++)
            acc += wp[dy * 3 + dx] * sx[ly + dy][lx + dx];

    int gpatch = (blockIdx.y * 2 + py2) * 32 + (blockIdx.x * 2 + px2);
    g_p[(size_t)plane * HW + (size_t)gpatch * 64 + wi] = acc;
}

// ---------------------------------------------------------------------------
// K3: fused patch-attention + 1x1 proj.
// Block = (b, patch-row py, patch-pair px2): 2 horizontal patches, 512 thr.
// Dynamic smem 85 KB: ws(16K) + q(64x68) + k(64x72, f4-swizzled) +
// att(64x128, 16B-group swizzled). 2 blocks/SM.
//   attn: thread=(ch,row i); out = (q (*) k)*temp*v -> att smem
//   proj: thread=(4oc x 4px); out written NCHW.
// ---------------------------------------------------------------------------
__device__ __forceinline__ int att_sw(int g) {       // g = in-row 16B group 0..31
    return g ^ ((g >> 3) & 3);
}

__global__ __launch_bounds__(512, 2) void k_attn_proj(
        const float* __restrict__ temperature,
        const float* __restrict__ pw,
        float* __restrict__ out) {
    extern __shared__ float sm[];
    float* ws    = sm;               // 4096
    float* qs    = sm + 4096;        // 64*68 = 4352
    float* ks    = qs + 4352;        // 64*72 = 4608
    float* att_s = ks + 4608;        // 64*128 = 8192

    int t   = threadIdx.x;
    int bid = blockIdx.x;
    int b   = bid >> 9;
    int r9  = bid & 511;
    int py  = r9 >> 4;               // patch row 0..31
    int px2 = r9 & 15;               // patch pair 0..15

    #pragma unroll
    for (int i = 0; i < 8; i++)
        ws[t + i * 512] = pw[t + i * 512];

    int ch = t >> 3, i = t & 7;
    float tmp = __ldg(temperature + ch);

    for (int p = 0; p < 2; p++) {
        int patch = py * 32 + px2 * 2 + p;
        __syncthreads();             // protect q/k reuse from previous iter

        // load q (ch 0..63) and k (ch 64..127): coalesced 256B per channel
        for (int idx = t; idx < 1024; idx += 512) {
            int lch = idx >> 4, rem = idx & 15;
            int p1 = rem >> 1, hf = (rem & 1) * 4;   // row, half
            const float* qsrc = g_p + ((size_t)(b * C3 + lch) * 1024 + patch) * 64
                              + p1 * 8 + hf;
            *(float4*)(qs + lch * 68 + p1 * 8 + hf) = *(const float4*)qsrc;
            float4 kv = *(const float4*)(qsrc + (size_t)64 * 1024 * 64);
            int g16 = (2 * p1 + (hf >> 2)) ^ (p1 >> 2);
            *(float4*)(ks + lch * 72 + g16 * 4) = kv;
        }
        __syncthreads();

        float o[8];
        #pragma unroll
        for (int j = 0; j < 8; j++) o[j] = 0.f;

        const float* qb = qs + ch * 68;
        const float* kb = ks + ch * 72;
        #pragma unroll
        for (int u = 0; u < 8; u++) {
            int r = (i - u) & 7;
            float4 qa = *(const float4*)(qb + u * 8);
            float4 qc = *(const float4*)(qb + u * 8 + 4);
            float qr[8] = {qa.x, qa.y, qa.z, qa.w, qc.x, qc.y, qc.z, qc.w};
            float4 k0 = *(const float4*)(kb + (((2 * r)     ^ (r >> 2)) * 4));
            float4 k1 = *(const float4*)(kb + (((2 * r + 1) ^ (r >> 2)) * 4));
            float kr[8] = {k0.x, k0.y, k0.z, k0.w, k1.x, k1.y, k1.z, k1.w};
            #pragma unroll
            for (int j = 0; j < 8; j++)
                #pragma unroll
                for (int v = 0; v < 8; v++)
                    o[j] += qr[v] * kr[(j - v) & 7];
        }

        // v (ch+128), apply temp, store to swizzled att
        const float* vsrc = g_p + ((size_t)(b * C3 + 128 + ch) * 1024 + patch) * 64
                          + i * 8;
        float4 v0 = *(const float4*)vsrc;
        float4 v1 = *(const float4*)(vsrc + 4);
        int g0 = att_sw(i * 4 + p * 2 + 0);
        int g1 = att_sw(i * 4 + p * 2 + 1);
        *(float4*)(att_s + ch * 128 + g0 * 4) =
            make_float4(o[0]*tmp*v0.x, o[1]*tmp*v0.y, o[2]*tmp*v0.z, o[3]*tmp*v0.w);
        *(float4*)(att_s + ch * 128 + g1 * 4) =
            make_float4(o[4]*tmp*v1.x, o[5]*tmp*v1.y, o[6]*tmp*v1.z, o[7]*tmp*v1.w);
    }
    __syncthreads();

    // ---- proj: 64oc x 128px, thread = 4oc x 4px ----
    int lane = t & 31;
    int oc0  = (t >> 5) * 4;
    int gphys = att_sw(lane);        // swizzled 16B group for this lane's px

    float acc[4][4];
    #pragma unroll
    for (int r = 0; r < 4; r++)
        #pragma unroll
        for (int j = 0; j < 4; j++) acc[r][j] = 0.f;

    #pragma unroll 4
    for (int kk = 0; kk < 64; kk++) {
        float4 a = *(const float4*)(att_s + kk * 128 + gphys * 4);
        float xv[4] = {a.x, a.y, a.z, a.w};
        #pragma unroll
        for (int r = 0; r < 4; r++) {
            float wv = ws[(oc0 + r) * 64 + kk];
            #pragma unroll
            for (int j = 0; j < 4; j++) acc[r][j] += wv * xv[j];
        }
    }

    // px logical = lane*4 + j: y = py*8 + (lane>>2), x = px2*16 + (lane&3)*4
    int y  = py * 8 + (lane >> 2);
    int xg = px2 * 16 + (lane & 3) * 4;
    float* ob = out + (size_t)b * C * HW + (size_t)y * Wdim + xg;
    #pragma unroll
    for (int r = 0; r < 4; r++)
        *(float4*)(ob + (size_t)(oc0 + r) * HW) =
            make_float4(acc[r][0], acc[r][1], acc[r][2], acc[r][3]);
}

// ---------------------------------------------------------------------------
extern "C" void kernel_launch(void* const* d_in, const int* in_sizes, int n_in,
                              void* d_out, int out_size) {
    const float* x           = (const float*)d_in[0];
    const float* qkv_w       = (const float*)d_in[1];
    const float* dw_w        = (const float*)d_in[2];
    const float* proj_w      = (const float*)d_in[3];
    const float* temperature = (const float*)d_in[4];
    float* out = (float*)d_out;

    static int smem_set = 0;
    if (!smem_set) {
        cudaFuncSetAttribute(k_attn_proj,
                             cudaFuncAttributeMaxDynamicSharedMemorySize, 84992);
        smem_set = 1;
    }

    k_qkv <<<dim3(B * 256, 3), 512>>>(x, qkv_w);
    k_dw  <<<dim3(16, 16, B * C3), 256>>>(dw_w);
    k_attn_proj<<<B * 512, 512, 84992>>>(temperature, proj_w, out);
}

// round 8
// speedup vs baseline: 1.1737x; 1.1737x over previous
#include <cuda_runtime.h>
#include <cstdint>

#define B    8
#define C    64
#define C3   192
#define Hdim 256
#define Wdim 256
#define HW   65536

// Scratch (device globals: allocation-free per harness rules)
__device__ float g_qkv[(size_t)B * C3 * HW];  // after 1x1 qkv conv (std NCHW)
__device__ float g_p  [(size_t)B * C3 * HW];  // after depthwise, patch-blocked:
                                              // [b*C3+ch][patchIdx(1024)][64]

// ---------------------------------------------------------------------------
// Packed fp32x2 helpers (Blackwell base-arch packed math; exact fp32 lanes)
// ---------------------------------------------------------------------------
typedef unsigned long long u64t;

__device__ __forceinline__ u64t pk2(float lo, float hi) {
    u64t d;
    asm("mov.b64 %0, {%1, %2};" : "=l"(d) : "f"(lo), "f"(hi));
    return d;
}
__device__ __forceinline__ void upk2(u64t v, float& lo, float& hi) {
    asm("mov.b64 {%0, %1}, %2;" : "=f"(lo), "=f"(hi) : "l"(v));
}
__device__ __forceinline__ u64t ffma2(u64t a, u64t b, u64t c) {
    u64t d;
    asm("fma.rn.f32x2 %0, %1, %2, %3;" : "=l"(d) : "l"(a), "l"(b), "l"(c));
    return d;
}

// ---------------------------------------------------------------------------
// K1: 1x1 qkv GEMM, f32x2. 64oc x 256px tile, 512 threads, 4oc x 8px/thread.
// grid (B*256, 3). Weights pre-duplicated {w,w} in smem -> LDS.64 broadcast.
// dyn smem: wsd 32KB + xs 32KB = 64KB.
// ---------------------------------------------------------------------------
__global__ __launch_bounds__(512, 2) void k_qkv(const float* __restrict__ x,
                                                const float* __restrict__ w) {
    extern __shared__ float sm[];
    u64t*  wsd = (u64t*)sm;          // [64 oc][64 ic] packed {w,w}
    float* xs  = sm + 8192;          // [32 ic][256 px]
    int b   = blockIdx.x >> 8;
    int px0 = (blockIdx.x & 255) << 8;
    int ocH = blockIdx.y * 64;
    int t   = threadIdx.x;

    #pragma unroll
    for (int i = 0; i < 8; i++) {
        float v = w[ocH * 64 + t + i * 512];
        wsd[t + i * 512] = pk2(v, v);
    }

    int lane = t & 31;
    int pxA  = lane * 4;
    int oc0  = (t >> 5) * 4;         // 16 warps x 4 oc

    u64t acc[4][4];
    #pragma unroll
    for (int r = 0; r < 4; r++)
        #pragma unroll
        for (int j = 0; j < 4; j++) acc[r][j] = 0ull;

    const float* xb = x + (size_t)b * C * HW + px0;

    for (int ckk = 0; ckk < 2; ckk++) {
        __syncthreads();
        #pragma unroll
        for (int i = 0; i < 4; i++) {
            int idx = t + i * 512;           // 0..2047 float4s
            int ic  = idx >> 6;
            int p4  = idx & 63;
            *(float4*)(xs + ic * 256 + p4 * 4) =
                *(const float4*)(xb + (size_t)(ckk * 32 + ic) * HW + p4 * 4);
        }
        __syncthreads();

        #pragma unroll 4
        for (int ic = 0; ic < 32; ic++) {
            float4 a0 = *(const float4*)(xs + ic * 256 + pxA);
            float4 a1 = *(const float4*)(xs + ic * 256 + pxA + 128);
            u64t x2[4] = {pk2(a0.x, a0.y), pk2(a0.z, a0.w),
                          pk2(a1.x, a1.y), pk2(a1.z, a1.w)};
            int kk = ckk * 32 + ic;
            #pragma unroll
            for (int r = 0; r < 4; r++) {
                u64t wp = wsd[(oc0 + r) * 64 + kk];
                #pragma unroll
                for (int j = 0; j < 4; j++) acc[r][j] = ffma2(wp, x2[j], acc[r][j]);
            }
        }
    }

    float* ob = g_qkv + (size_t)b * C3 * HW + px0;
    #pragma unroll
    for (int r = 0; r < 4; r++) {
        float o0, o1, o2, o3, o4, o5, o6, o7;
        upk2(acc[r][0], o0, o1); upk2(acc[r][1], o2, o3);
        upk2(acc[r][2], o4, o5); upk2(acc[r][3], o6, o7);
        float* dst = ob + (size_t)(ocH + oc0 + r) * HW;
        *(float4*)(dst + pxA)       = make_float4(o0, o1, o2, o3);
        *(float4*)(dst + pxA + 128) = make_float4(o4, o5, o6, o7);
    }
}

// ---------------------------------------------------------------------------
// K2: 3x3 depthwise conv, row-streaming. Block = one (b,ch) plane, 256 thr =
// one full row. 3-row rolling smem buffer, coalesced 1024B row loads.
// Writes patch-blocked g_p.
// ---------------------------------------------------------------------------
__global__ __launch_bounds__(256) void k_dw(const float* __restrict__ dw) {
    __shared__ float rows[3][258];
    int plane = blockIdx.x;
    int ch    = plane % C3;
    const float* ip = g_qkv + (size_t)plane * HW;
    float* op = g_p + (size_t)plane * HW;
    int t = threadIdx.x;

    float wreg[9];
    #pragma unroll
    for (int i = 0; i < 9; i++) wreg[i] = __ldg(dw + ch * 9 + i);

    // edge columns always zero
    if (t < 6) rows[t >> 1][(t & 1) ? 257 : 0] = 0.f;
    // slot(r) = (r+1)%3 ; row -1 -> slot 0 zeros; row 0 -> slot 1
    rows[0][t + 1] = 0.f;
    rows[1][t + 1] = ip[t];

    for (int y = 0; y < 256; y++) {
        int s_next = (y + 2) % 3;        // will hold row y+1
        __syncthreads();                 // prior reads of s_next done
        rows[s_next][t + 1] = (y < 255) ? ip[(y + 1) * 256 + t] : 0.f;
        __syncthreads();

        const float* rm = rows[y % 3];         // row y-1
        const float* rc = rows[(y + 1) % 3];   // row y
        const float* rp = rows[s_next];        // row y+1
        float acc = wreg[0] * rm[t] + wreg[1] * rm[t + 1] + wreg[2] * rm[t + 2]
                  + wreg[3] * rc[t] + wreg[4] * rc[t + 1] + wreg[5] * rc[t + 2]
                  + wreg[6] * rp[t] + wreg[7] * rp[t + 1] + wreg[8] * rp[t + 2];

        int gpatch = (y >> 3) * 32 + (t >> 3);
        int wi     = (y & 7) * 8 + (t & 7);
        op[(size_t)gpatch * 64 + wi] = acc;
    }
}

// ---------------------------------------------------------------------------
// K3: fused patch-attention + 1x1 proj, f32x2.
// Block = (b, patch-row, patch-pair), 512 thr, dyn smem ~99KB, 2 blocks/SM.
// ---------------------------------------------------------------------------
__device__ __forceinline__ int att_sw(int g) { return g ^ ((g >> 3) & 3); }

__global__ __launch_bounds__(512, 2) void k_attn_proj(
        const float* __restrict__ temperature,
        const float* __restrict__ pw,
        float* __restrict__ out) {
    extern __shared__ float sm[];
    u64t*  wsd   = (u64t*)sm;        // [64 oc][64 ic] packed {w,w}  (32 KB)
    float* qs    = sm + 8192;        // 64*68
    float* ks    = qs + 4352;        // 64*72  (f4-group swizzled)
    float* att_s = ks + 4608;        // 64*128 (16B-group swizzled)

    int t   = threadIdx.x;
    int bid = blockIdx.x;
    int b   = bid >> 9;
    int r9  = bid & 511;
    int py  = r9 >> 4;
    int px2 = r9 & 15;

    #pragma unroll
    for (int i = 0; i < 8; i++) {
        float v = pw[t + i * 512];
        wsd[t + i * 512] = pk2(v, v);
    }

    int ch = t >> 3, i = t & 7;
    float tmp = __ldg(temperature + ch);

    for (int p = 0; p < 2; p++) {
        int patch = py * 32 + px2 * 2 + p;
        __syncthreads();

        for (int idx = t; idx < 1024; idx += 512) {
            int lch = idx >> 4, rem = idx & 15;
            int p1 = rem >> 1, hf = (rem & 1) * 4;
            const float* qsrc = g_p + ((size_t)(b * C3 + lch) * 1024 + patch) * 64
                              + p1 * 8 + hf;
            *(float4*)(qs + lch * 68 + p1 * 8 + hf) = *(const float4*)qsrc;
            float4 kv = *(const float4*)(qsrc + (size_t)64 * 1024 * 64);
            int g16 = (2 * p1 + (hf >> 2)) ^ (p1 >> 2);
            *(float4*)(ks + lch * 72 + g16 * 4) = kv;
        }
        __syncthreads();

        u64t o2[8];
        #pragma unroll
        for (int j = 0; j < 8; j++) o2[j] = 0ull;

        const float* qb = qs + ch * 68;
        const float* kb = ks + ch * 72;
        #pragma unroll
        for (int u = 0; u < 8; u++) {
            int r = (i - u) & 7;
            float4 qa = *(const float4*)(qb + u * 8);
            float4 qc = *(const float4*)(qb + u * 8 + 4);
            u64t q2[4] = {pk2(qa.x, qa.y), pk2(qa.z, qa.w),
                          pk2(qc.x, qc.y), pk2(qc.z, qc.w)};
            float4 k0 = *(const float4*)(kb + (((2 * r)     ^ (r >> 2)) * 4));
            float4 k1 = *(const float4*)(kb + (((2 * r + 1) ^ (r >> 2)) * 4));
            float kr[8] = {k0.x, k0.y, k0.z, k0.w, k1.x, k1.y, k1.z, k1.w};
            u64t rk[8];                         // rk[m] = {kr[m], kr[(m-1)&7]}
            #pragma unroll
            for (int m = 0; m < 8; m++) rk[m] = pk2(kr[m], kr[(m + 7) & 7]);
            #pragma unroll
            for (int j = 0; j < 8; j++)
                #pragma unroll
                for (int a = 0; a < 4; a++)
                    o2[j] = ffma2(q2[a], rk[(j - 2 * a) & 7], o2[j]);
        }
        float o[8];
        #pragma unroll
        for (int j = 0; j < 8; j++) {
            float lo, hi;
            upk2(o2[j], lo, hi);
            o[j] = lo + hi;
        }

        const float* vsrc = g_p + ((size_t)(b * C3 + 128 + ch) * 1024 + patch) * 64
                          + i * 8;
        float4 v0 = *(const float4*)vsrc;
        float4 v1 = *(const float4*)(vsrc + 4);
        int g0 = att_sw(i * 4 + p * 2 + 0);
        int g1 = att_sw(i * 4 + p * 2 + 1);
        *(float4*)(att_s + ch * 128 + g0 * 4) =
            make_float4(o[0]*tmp*v0.x, o[1]*tmp*v0.y, o[2]*tmp*v0.z, o[3]*tmp*v0.w);
        *(float4*)(att_s + ch * 128 + g1 * 4) =
            make_float4(o[4]*tmp*v1.x, o[5]*tmp*v1.y, o[6]*tmp*v1.z, o[7]*tmp*v1.w);
    }
    __syncthreads();

    // ---- proj: 64oc x 128px, thread = 4oc x 4px, f32x2 ----
    int lane = t & 31;
    int oc0  = (t >> 5) * 4;
    int gphys = att_sw(lane);

    u64t acc[4][2];
    #pragma unroll
    for (int r = 0; r < 4; r++) { acc[r][0] = 0ull; acc[r][1] = 0ull; }

    #pragma unroll 4
    for (int kk = 0; kk < 64; kk++) {
        float4 a = *(const float4*)(att_s + kk * 128 + gphys * 4);
        u64t x2[2] = {pk2(a.x, a.y), pk2(a.z, a.w)};
        #pragma unroll
        for (int r = 0; r < 4; r++) {
            u64t wp = wsd[(oc0 + r) * 64 + kk];
            acc[r][0] = ffma2(wp, x2[0], acc[r][0]);
            acc[r][1] = ffma2(wp, x2[1], acc[r][1]);
        }
    }

    int y  = py * 8 + (lane >> 2);
    int xg = px2 * 16 + (lane & 3) * 4;
    float* ob = out + (size_t)b * C * HW + (size_t)y * Wdim + xg;
    #pragma unroll
    for (int r = 0; r < 4; r++) {
        float o0, o1, o2v, o3;
        upk2(acc[r][0], o0, o1);
        upk2(acc[r][1], o2v, o3);
        *(float4*)(ob + (size_t)(oc0 + r) * HW) = make_float4(o0, o1, o2v, o3);
    }
}

// ---------------------------------------------------------------------------
extern "C" void kernel_launch(void* const* d_in, const int* in_sizes, int n_in,
                              void* d_out, int out_size) {
    const float* x           = (const float*)d_in[0];
    const float* qkv_w       = (const float*)d_in[1];
    const float* dw_w        = (const float*)d_in[2];
    const float* proj_w      = (const float*)d_in[3];
    const float* temperature = (const float*)d_in[4];
    float* out = (float*)d_out;

    cudaFuncSetAttribute(k_qkv,
                         cudaFuncAttributeMaxDynamicSharedMemorySize, 65536);
    cudaFuncSetAttribute(k_attn_proj,
                         cudaFuncAttributeMaxDynamicSharedMemorySize, 101376);

    k_qkv <<<dim3(B * 256, 3), 512, 65536>>>(x, qkv_w);
    k_dw  <<<B * C3, 256>>>(dw_w);
    k_attn_proj<<<B * 512, 512, 101376>>>(temperature, proj_w, out);
}

// round 9
// speedup vs baseline: 1.3984x; 1.1914x over previous
#include <cuda_runtime.h>
#include <cstdint>

#define B    8
#define C    64
#define C3   192
#define Hdim 256
#define Wdim 256
#define HW   65536

// Scratch (device globals: allocation-free per harness rules)
__device__ float g_qkv[(size_t)B * C3 * HW];  // after 1x1 qkv conv (std NCHW)
__device__ float g_p  [(size_t)B * C3 * HW];  // after depthwise, patch-blocked:
                                              // [b*C3+ch][patchIdx(1024)][64]

// ---------------------------------------------------------------------------
// Packed fp32x2 helpers (Blackwell base-arch packed math; exact fp32 lanes)
// ---------------------------------------------------------------------------
typedef unsigned long long u64t;

__device__ __forceinline__ u64t pk2(float lo, float hi) {
    u64t d;
    asm("mov.b64 %0, {%1, %2};" : "=l"(d) : "f"(lo), "f"(hi));
    return d;
}
__device__ __forceinline__ void upk2(u64t v, float& lo, float& hi) {
    asm("mov.b64 {%0, %1}, %2;" : "=f"(lo), "=f"(hi) : "l"(v));
}
__device__ __forceinline__ u64t ffma2(u64t a, u64t b, u64t c) {
    u64t d;
    asm("fma.rn.f32x2 %0, %1, %2, %3;" : "=l"(d) : "l"(a), "l"(b), "l"(c));
    return d;
}

// ---------------------------------------------------------------------------
// K1: 1x1 qkv GEMM. CTA = 128-px tile, ALL 192 oc (x read once).
// 512 threads = 16 warps; warp = 6 oc-pairs (12 oc), lane = 4 px.
// oc-pairs packed in f32x2 lanes: w-pair LDS.64 broadcast (1 wf), x LDS.128
// (4 wf) -> 10 wf per ic per warp for 48 FMA.
// dyn smem: wp2 48KB + xs 32KB = 80KB.
// ---------------------------------------------------------------------------
__global__ __launch_bounds__(512) void k_qkv(const float* __restrict__ x,
                                             const float* __restrict__ w) {
    extern __shared__ float sm[];
    u64t*  wp2 = (u64t*)sm;          // [96 pair][64 ic] = {w[2p][ic], w[2p+1][ic]}
    float* xs  = sm + 12288;         // [64 ic][128 px]
    int b   = blockIdx.x >> 9;
    int px0 = (blockIdx.x & 511) << 7;
    int t   = threadIdx.x;

    // weights: 96 pairs x 64 ic (each half-row read coalesced 128B)
    #pragma unroll
    for (int k = 0; k < 12; k++) {
        int i  = t + k * 512;        // 0..6143 = pair*64 + ic
        int pr = i >> 6, ic = i & 63;
        wp2[i] = pk2(w[(2 * pr) * 64 + ic], w[(2 * pr + 1) * 64 + ic]);
    }
    // x tile: 64 ic x 128 px
    const float* xb = x + (size_t)b * C * HW + px0;
    #pragma unroll
    for (int k = 0; k < 4; k++) {
        int i  = t + k * 512;        // 0..2047 float4s
        int ic = i >> 5, p4 = i & 31;
        *(float4*)(xs + ic * 128 + p4 * 4) =
            *(const float4*)(xb + (size_t)ic * HW + p4 * 4);
    }
    __syncthreads();

    int lane   = t & 31;
    int wpair0 = (t >> 5) * 6;       // warp's first oc-pair

    u64t acc[6][4];
    #pragma unroll
    for (int r = 0; r < 6; r++)
        #pragma unroll
        for (int j = 0; j < 4; j++) acc[r][j] = 0ull;

    #pragma unroll 4
    for (int ic = 0; ic < 64; ic++) {
        float4 a = *(const float4*)(xs + ic * 128 + lane * 4);
        u64t xd[4] = {pk2(a.x, a.x), pk2(a.y, a.y), pk2(a.z, a.z), pk2(a.w, a.w)};
        #pragma unroll
        for (int r = 0; r < 6; r++) {
            u64t wp = wp2[(wpair0 + r) * 64 + ic];
            #pragma unroll
            for (int j = 0; j < 4; j++) acc[r][j] = ffma2(wp, xd[j], acc[r][j]);
        }
    }

    float* ob = g_qkv + (size_t)b * C3 * HW + px0 + lane * 4;
    #pragma unroll
    for (int r = 0; r < 6; r++) {
        int oc0 = (wpair0 + r) * 2;
        float e0, o0, e1, o1, e2, o2, e3, o3;
        upk2(acc[r][0], e0, o0); upk2(acc[r][1], e1, o1);
        upk2(acc[r][2], e2, o2); upk2(acc[r][3], e3, o3);
        *(float4*)(ob + (size_t)oc0 * HW)       = make_float4(e0, e1, e2, e3);
        *(float4*)(ob + (size_t)(oc0 + 1) * HW) = make_float4(o0, o1, o2, o3);
    }
}

// ---------------------------------------------------------------------------
// K2: 3x3 depthwise conv, row-streaming, 2 rows per iteration (4-slot ring).
// Block = one (b,ch) plane, 256 thr = one full row. Writes patch-blocked g_p.
// slot(r) = (r+1)&3.
// ---------------------------------------------------------------------------
__global__ __launch_bounds__(256) void k_dw(const float* __restrict__ dw) {
    __shared__ float rows[4][258];
    int plane = blockIdx.x;
    int ch    = plane % C3;
    const float* ip = g_qkv + (size_t)plane * HW;
    float* op = g_p + (size_t)plane * HW;
    int t = threadIdx.x;

    float wreg[9];
    #pragma unroll
    for (int i = 0; i < 9; i++) wreg[i] = __ldg(dw + ch * 9 + i);

    // edge columns always zero (4 slots x 2 edges)
    if (t < 8) rows[t >> 1][(t & 1) ? 257 : 0] = 0.f;
    rows[0][t + 1] = 0.f;            // row -1
    rows[1][t + 1] = ip[t];          // row 0

    for (int y = 0; y < 256; y += 2) {
        int sA = (y + 2) & 3;        // will hold row y+1
        int sB = (y + 3) & 3;        // will hold row y+2
        __syncthreads();             // prior reads of sA/sB done
        rows[sA][t + 1] = ip[(y + 1) * 256 + t];
        rows[sB][t + 1] = (y + 2 < 256) ? ip[(y + 2) * 256 + t] : 0.f;
        __syncthreads();

        const float* r0 = rows[y & 3];        // row y-1
        const float* r1 = rows[(y + 1) & 3];  // row y
        const float* r2 = rows[sA];           // row y+1
        const float* r3 = rows[sB];           // row y+2

        float a0 = wreg[0]*r0[t] + wreg[1]*r0[t+1] + wreg[2]*r0[t+2]
                 + wreg[3]*r1[t] + wreg[4]*r1[t+1] + wreg[5]*r1[t+2]
                 + wreg[6]*r2[t] + wreg[7]*r2[t+1] + wreg[8]*r2[t+2];
        float a1 = wreg[0]*r1[t] + wreg[1]*r1[t+1] + wreg[2]*r1[t+2]
                 + wreg[3]*r2[t] + wreg[4]*r2[t+1] + wreg[5]*r2[t+2]
                 + wreg[6]*r3[t] + wreg[7]*r3[t+1] + wreg[8]*r3[t+2];

        int gp0 = (y >> 3) * 32 + (t >> 3);
        int wi0 = (y & 7) * 8 + (t & 7);
        op[(size_t)gp0 * 64 + wi0] = a0;
        int gp1 = ((y + 1) >> 3) * 32 + (t >> 3);
        int wi1 = ((y + 1) & 7) * 8 + (t & 7);
        op[(size_t)gp1 * 64 + wi1] = a1;
    }
}

// ---------------------------------------------------------------------------
// K3: fused patch-attention + 1x1 proj, f32x2 (unchanged from R8).
// ---------------------------------------------------------------------------
__device__ __forceinline__ int att_sw(int g) { return g ^ ((g >> 3) & 3); }

__global__ __launch_bounds__(512, 2) void k_attn_proj(
        const float* __restrict__ temperature,
        const float* __restrict__ pw,
        float* __restrict__ out) {
    extern __shared__ float sm[];
    u64t*  wsd   = (u64t*)sm;        // [64 oc][64 ic] packed {w,w}  (32 KB)
    float* qs    = sm + 8192;        // 64*68
    float* ks    = qs + 4352;        // 64*72  (f4-group swizzled)
    float* att_s = ks + 4608;        // 64*128 (16B-group swizzled)

    int t   = threadIdx.x;
    int bid = blockIdx.x;
    int b   = bid >> 9;
    int r9  = bid & 511;
    int py  = r9 >> 4;
    int px2 = r9 & 15;

    #pragma unroll
    for (int i = 0; i < 8; i++) {
        float v = pw[t + i * 512];
        wsd[t + i * 512] = pk2(v, v);
    }

    int ch = t >> 3, i = t & 7;
    float tmp = __ldg(temperature + ch);

    for (int p = 0; p < 2; p++) {
        int patch = py * 32 + px2 * 2 + p;
        __syncthreads();

        for (int idx = t; idx < 1024; idx += 512) {
            int lch = idx >> 4, rem = idx & 15;
            int p1 = rem >> 1, hf = (rem & 1) * 4;
            const float* qsrc = g_p + ((size_t)(b * C3 + lch) * 1024 + patch) * 64
                              + p1 * 8 + hf;
            *(float4*)(qs + lch * 68 + p1 * 8 + hf) = *(const float4*)qsrc;
            float4 kv = *(const float4*)(qsrc + (size_t)64 * 1024 * 64);
            int g16 = (2 * p1 + (hf >> 2)) ^ (p1 >> 2);
            *(float4*)(ks + lch * 72 + g16 * 4) = kv;
        }
        __syncthreads();

        u64t o2[8];
        #pragma unroll
        for (int j = 0; j < 8; j++) o2[j] = 0ull;

        const float* qb = qs + ch * 68;
        const float* kb = ks + ch * 72;
        #pragma unroll
        for (int u = 0; u < 8; u++) {
            int r = (i - u) & 7;
            float4 qa = *(const float4*)(qb + u * 8);
            float4 qc = *(const float4*)(qb + u * 8 + 4);
            u64t q2[4] = {pk2(qa.x, qa.y), pk2(qa.z, qa.w),
                          pk2(qc.x, qc.y), pk2(qc.z, qc.w)};
            float4 k0 = *(const float4*)(kb + (((2 * r)     ^ (r >> 2)) * 4));
            float4 k1 = *(const float4*)(kb + (((2 * r + 1) ^ (r >> 2)) * 4));
            float kr[8] = {k0.x, k0.y, k0.z, k0.w, k1.x, k1.y, k1.z, k1.w};
            u64t rk[8];                         // rk[m] = {kr[m], kr[(m-1)&7]}
            #pragma unroll
            for (int m = 0; m < 8; m++) rk[m] = pk2(kr[m], kr[(m + 7) & 7]);
            #pragma unroll
            for (int j = 0; j < 8; j++)
                #pragma unroll
                for (int a = 0; a < 4; a++)
                    o2[j] = ffma2(q2[a], rk[(j - 2 * a) & 7], o2[j]);
        }
        float o[8];
        #pragma unroll
        for (int j = 0; j < 8; j++) {
            float lo, hi;
            upk2(o2[j], lo, hi);
            o[j] = lo + hi;
        }

        const float* vsrc = g_p + ((size_t)(b * C3 + 128 + ch) * 1024 + patch) * 64
                          + i * 8;
        float4 v0 = *(const float4*)vsrc;
        float4 v1 = *(const float4*)(vsrc + 4);
        int g0 = att_sw(i * 4 + p * 2 + 0);
        int g1 = att_sw(i * 4 + p * 2 + 1);
        *(float4*)(att_s + ch * 128 + g0 * 4) =
            make_float4(o[0]*tmp*v0.x, o[1]*tmp*v0.y, o[2]*tmp*v0.z, o[3]*tmp*v0.w);
        *(float4*)(att_s + ch * 128 + g1 * 4) =
            make_float4(o[4]*tmp*v1.x, o[5]*tmp*v1.y, o[6]*tmp*v1.z, o[7]*tmp*v1.w);
    }
    __syncthreads();

    // ---- proj: 64oc x 128px, thread = 4oc x 4px, f32x2 ----
    int lane = t & 31;
    int oc0  = (t >> 5) * 4;
    int gphys = att_sw(lane);

    u64t acc[4][2];
    #pragma unroll
    for (int r = 0; r < 4; r++) { acc[r][0] = 0ull; acc[r][1] = 0ull; }

    #pragma unroll 4
    for (int kk = 0; kk < 64; kk++) {
        float4 a = *(const float4*)(att_s + kk * 128 + gphys * 4);
        u64t x2[2] = {pk2(a.x, a.y), pk2(a.z, a.w)};
        #pragma unroll
        for (int r = 0; r < 4; r++) {
            u64t wp = wsd[(oc0 + r) * 64 + kk];
            acc[r][0] = ffma2(wp, x2[0], acc[r][0]);
            acc[r][1] = ffma2(wp, x2[1], acc[r][1]);
        }
    }

    int y  = py * 8 + (lane >> 2);
    int xg = px2 * 16 + (lane & 3) * 4;
    float* ob = out + (size_t)b * C * HW + (size_t)y * Wdim + xg;
    #pragma unroll
    for (int r = 0; r < 4; r++) {
        float o0, o1, o2v, o3;
        upk2(acc[r][0], o0, o1);
        upk2(acc[r][1], o2v, o3);
        *(float4*)(ob + (size_t)(oc0 + r) * HW) = make_float4(o0, o1, o2v, o3);
    }
}

// ---------------------------------------------------------------------------
extern "C" void kernel_launch(void* const* d_in, const int* in_sizes, int n_in,
                              void* d_out, int out_size) {
    const float* x           = (const float*)d_in[0];
    const float* qkv_w       = (const float*)d_in[1];
    const float* dw_w        = (const float*)d_in[2];
    const float* proj_w      = (const float*)d_in[3];
    const float* temperature = (const float*)d_in[4];
    float* out = (float*)d_out;

    cudaFuncSetAttribute(k_qkv,
                         cudaFuncAttributeMaxDynamicSharedMemorySize, 81920);
    cudaFuncSetAttribute(k_attn_proj,
                         cudaFuncAttributeMaxDynamicSharedMemorySize, 101376);

    k_qkv <<<B * 512, 512, 81920>>>(x, qkv_w);
    k_dw  <<<B * C3, 256>>>(dw_w);
    k_attn_proj<<<B * 512, 512, 101376>>>(temperature, proj_w, out);
}

// round 14
// speedup vs baseline: 1.4559x; 1.0411x over previous
#include <cuda_runtime.h>
#include <cstdint>

#define B    8
#define C    64
#define C3   192
#define Hdim 256
#define Wdim 256
#define HW   65536

// Scratch (device globals: allocation-free per harness rules)
__device__ float g_qkv[(size_t)B * C3 * HW];  // after 1x1 qkv conv (std NCHW)
__device__ float g_p  [(size_t)B * C3 * HW];  // after depthwise, patch-blocked:
                                              // [b*C3+ch][patchIdx(1024)][64]

// ---------------------------------------------------------------------------
// Packed fp32x2 helpers (Blackwell base-arch packed math; exact fp32 lanes)
// ---------------------------------------------------------------------------
typedef unsigned long long u64t;

__device__ __forceinline__ u64t pk2(float lo, float hi) {
    u64t d;
    asm("mov.b64 %0, {%1, %2};" : "=l"(d) : "f"(lo), "f"(hi));
    return d;
}
__device__ __forceinline__ void upk2(u64t v, float& lo, float& hi) {
    asm("mov.b64 {%0, %1}, %2;" : "=f"(lo), "=f"(hi) : "l"(v));
}
__device__ __forceinline__ u64t ffma2(u64t a, u64t b, u64t c) {
    u64t d;
    asm("fma.rn.f32x2 %0, %1, %2, %3;" : "=l"(d) : "l"(a), "l"(b), "l"(c));
    return d;
}

// ---------------------------------------------------------------------------
// K1: 1x1 qkv GEMM. CTA = 128-px tile x 96 oc; 256 threads = 8 warps;
// warp = 6 oc-pairs (12 oc) packed in f32x2 lanes, lane = 4 px.
// Per ic per warp: 1 LDS.128 (4wf) + 6 LDS.64 broadcast (6wf) -> 48 FMA.
// Target 3 CTAs/SM (<=85 regs via launch_bounds, 56KB smem) = 24 warps.
// ---------------------------------------------------------------------------
__global__ __launch_bounds__(256, 3) void k_qkv(const float* __restrict__ x,
                                                const float* __restrict__ w) {
    extern __shared__ float sm[];
    u64t*  wp2 = (u64t*)sm;          // [48 pair][64 ic] = {w[2p][ic], w[2p+1][ic]}
    float* xs  = sm + 6144;          // [64 ic][128 px]
    int b   = blockIdx.x >> 9;
    int px0 = (blockIdx.x & 511) << 7;
    int ocH = blockIdx.y * 96;
    int t   = threadIdx.x;

    // weights: 48 pairs x 64 ic
    #pragma unroll
    for (int k = 0; k < 12; k++) {
        int i  = t + k * 256;        // 0..3071 = pair*64 + ic
        int pr = i >> 6, ic = i & 63;
        wp2[i] = pk2(w[(ocH + 2 * pr) * 64 + ic], w[(ocH + 2 * pr + 1) * 64 + ic]);
    }
    // x tile: 64 ic x 128 px
    const float* xb = x + (size_t)b * C * HW + px0;
    #pragma unroll
    for (int k = 0; k < 8; k++) {
        int i  = t + k * 256;        // 0..2047 float4s
        int ic = i >> 5, p4 = i & 31;
        *(float4*)(xs + ic * 128 + p4 * 4) =
            *(const float4*)(xb + (size_t)ic * HW + p4 * 4);
    }
    __syncthreads();

    int lane   = t & 31;
    int wpair0 = (t >> 5) * 6;       // warp's first local oc-pair (0..42)

    u64t acc[6][4];
    #pragma unroll
    for (int r = 0; r < 6; r++)
        #pragma unroll
        for (int j = 0; j < 4; j++) acc[r][j] = 0ull;

    #pragma unroll 4
    for (int ic = 0; ic < 64; ic++) {
        float4 a = *(const float4*)(xs + ic * 128 + lane * 4);
        u64t xd[4] = {pk2(a.x, a.x), pk2(a.y, a.y), pk2(a.z, a.z), pk2(a.w, a.w)};
        #pragma unroll
        for (int r = 0; r < 6; r++) {
            u64t wp = wp2[(wpair0 + r) * 64 + ic];
            #pragma unroll
            for (int j = 0; j < 4; j++) acc[r][j] = ffma2(wp, xd[j], acc[r][j]);
        }
    }

    float* ob = g_qkv + (size_t)b * C3 * HW + px0 + lane * 4;
    #pragma unroll
    for (int r = 0; r < 6; r++) {
        int oc0 = ocH + 2 * (wpair0 + r);
        float e0, o0, e1, o1, e2, o2, e3, o3;
        upk2(acc[r][0], e0, o0); upk2(acc[r][1], e1, o1);
        upk2(acc[r][2], e2, o2); upk2(acc[r][3], e3, o3);
        *(float4*)(ob + (size_t)oc0 * HW)       = make_float4(e0, e1, e2, e3);
        *(float4*)(ob + (size_t)(oc0 + 1) * HW) = make_float4(o0, o1, o2, o3);
    }
}

// ---------------------------------------------------------------------------
// K2: 3x3 depthwise conv, row-streaming, 2 rows per iteration (4-slot ring).
// Block = one (b,ch) plane, 256 thr = one full row. Writes patch-blocked g_p.
// ---------------------------------------------------------------------------
__global__ __launch_bounds__(256) void k_dw(const float* __restrict__ dw) {
    __shared__ float rows[4][258];
    int plane = blockIdx.x;
    int ch    = plane % C3;
    const float* ip = g_qkv + (size_t)plane * HW;
    float* op = g_p + (size_t)plane * HW;
    int t = threadIdx.x;

    float wreg[9];
    #pragma unroll
    for (int i = 0; i < 9; i++) wreg[i] = __ldg(dw + ch * 9 + i);

    if (t < 8) rows[t >> 1][(t & 1) ? 257 : 0] = 0.f;
    rows[0][t + 1] = 0.f;            // row -1
    rows[1][t + 1] = ip[t];          // row 0

    for (int y = 0; y < 256; y += 2) {
        int sA = (y + 2) & 3;        // will hold row y+1
        int sB = (y + 3) & 3;        // will hold row y+2
        __syncthreads();
        rows[sA][t + 1] = ip[(y + 1) * 256 + t];
        rows[sB][t + 1] = (y + 2 < 256) ? ip[(y + 2) * 256 + t] : 0.f;
        __syncthreads();

        const float* r0 = rows[y & 3];
        const float* r1 = rows[(y + 1) & 3];
        const float* r2 = rows[sA];
        const float* r3 = rows[sB];

        float a0 = wreg[0]*r0[t] + wreg[1]*r0[t+1] + wreg[2]*r0[t+2]
                 + wreg[3]*r1[t] + wreg[4]*r1[t+1] + wreg[5]*r1[t+2]
                 + wreg[6]*r2[t] + wreg[7]*r2[t+1] + wreg[8]*r2[t+2];
        float a1 = wreg[0]*r1[t] + wreg[1]*r1[t+1] + wreg[2]*r1[t+2]
                 + wreg[3]*r2[t] + wreg[4]*r2[t+1] + wreg[5]*r2[t+2]
                 + wreg[6]*r3[t] + wreg[7]*r3[t+1] + wreg[8]*r3[t+2];

        int gp0 = (y >> 3) * 32 + (t >> 3);
        int wi0 = (y & 7) * 8 + (t & 7);
        op[(size_t)gp0 * 64 + wi0] = a0;
        int gp1 = ((y + 1) >> 3) * 32 + (t >> 3);
        int wi1 = ((y + 1) & 7) * 8 + (t & 7);
        op[(size_t)gp1 * 64 + wi1] = a1;
    }
}

// ---------------------------------------------------------------------------
// K3: fused patch-attention + 1x1 proj, f32x2 (unchanged).
// ---------------------------------------------------------------------------
__device__ __forceinline__ int att_sw(int g) { return g ^ ((g >> 3) & 3); }

__global__ __launch_bounds__(512, 2) void k_attn_proj(
        const float* __restrict__ temperature,
        const float* __restrict__ pw,
        float* __restrict__ out) {
    extern __shared__ float sm[];
    u64t*  wsd   = (u64t*)sm;        // [64 oc][64 ic] packed {w,w}  (32 KB)
    float* qs    = sm + 8192;        // 64*68
    float* ks    = qs + 4352;        // 64*72  (f4-group swizzled)
    float* att_s = ks + 4608;        // 64*128 (16B-group swizzled)

    int t   = threadIdx.x;
    int bid = blockIdx.x;
    int b   = bid >> 9;
    int r9  = bid & 511;
    int py  = r9 >> 4;
    int px2 = r9 & 15;

    #pragma unroll
    for (int i = 0; i < 8; i++) {
        float v = pw[t + i * 512];
        wsd[t + i * 512] = pk2(v, v);
    }

    int ch = t >> 3, i = t & 7;
    float tmp = __ldg(temperature + ch);

    for (int p = 0; p < 2; p++) {
        int patch = py * 32 + px2 * 2 + p;
        __syncthreads();

        for (int idx = t; idx < 1024; idx += 512) {
            int lch = idx >> 4, rem = idx & 15;
            int p1 = rem >> 1, hf = (rem & 1) * 4;
            const float* qsrc = g_p + ((size_t)(b * C3 + lch) * 1024 + patch) * 64
                              + p1 * 8 + hf;
            *(float4*)(qs + lch * 68 + p1 * 8 + hf) = *(const float4*)qsrc;
            float4 kv = *(const float4*)(qsrc + (size_t)64 * 1024 * 64);
            int g16 = (2 * p1 + (hf >> 2)) ^ (p1 >> 2);
            *(float4*)(ks + lch * 72 + g16 * 4) = kv;
        }
        __syncthreads();

        u64t o2[8];
        #pragma unroll
        for (int j = 0; j < 8; j++) o2[j] = 0ull;

        const float* qb = qs + ch * 68;
        const float* kb = ks + ch * 72;
        #pragma unroll
        for (int u = 0; u < 8; u++) {
            int r = (i - u) & 7;
            float4 qa = *(const float4*)(qb + u * 8);
            float4 qc = *(const float4*)(qb + u * 8 + 4);
            u64t q2[4] = {pk2(qa.x, qa.y), pk2(qa.z, qa.w),
                          pk2(qc.x, qc.y), pk2(qc.z, qc.w)};
            float4 k0 = *(const float4*)(kb + (((2 * r)     ^ (r >> 2)) * 4));
            float4 k1 = *(const float4*)(kb + (((2 * r + 1) ^ (r >> 2)) * 4));
            float kr[8] = {k0.x, k0.y, k0.z, k0.w, k1.x, k1.y, k1.z, k1.w};
            u64t rk[8];                         // rk[m] = {kr[m], kr[(m-1)&7]}
            #pragma unroll
            for (int m = 0; m < 8; m++) rk[m] = pk2(kr[m], kr[(m + 7) & 7]);
            #pragma unroll
            for (int j = 0; j < 8; j++)
                #pragma unroll
                for (int a = 0; a < 4; a++)
                    o2[j] = ffma2(q2[a], rk[(j - 2 * a) & 7], o2[j]);
        }
        float o[8];
        #pragma unroll
        for (int j = 0; j < 8; j++) {
            float lo, hi;
            upk2(o2[j], lo, hi);
            o[j] = lo + hi;
        }

        const float* vsrc = g_p + ((size_t)(b * C3 + 128 + ch) * 1024 + patch) * 64
                          + i * 8;
        float4 v0 = *(const float4*)vsrc;
        float4 v1 = *(const float4*)(vsrc + 4);
        int g0 = att_sw(i * 4 + p * 2 + 0);
        int g1 = att_sw(i * 4 + p * 2 + 1);
        *(float4*)(att_s + ch * 128 + g0 * 4) =
            make_float4(o[0]*tmp*v0.x, o[1]*tmp*v0.y, o[2]*tmp*v0.z, o[3]*tmp*v0.w);
        *(float4*)(att_s + ch * 128 + g1 * 4) =
            make_float4(o[4]*tmp*v1.x, o[5]*tmp*v1.y, o[6]*tmp*v1.z, o[7]*tmp*v1.w);
    }
    __syncthreads();

    // ---- proj: 64oc x 128px, thread = 4oc x 4px, f32x2 ----
    int lane = t & 31;
    int oc0  = (t >> 5) * 4;
    int gphys = att_sw(lane);

    u64t acc[4][2];
    #pragma unroll
    for (int r = 0; r < 4; r++) { acc[r][0] = 0ull; acc[r][1] = 0ull; }

    #pragma unroll 4
    for (int kk = 0; kk < 64; kk++) {
        float4 a = *(const float4*)(att_s + kk * 128 + gphys * 4);
        u64t x2[2] = {pk2(a.x, a.y), pk2(a.z, a.w)};
        #pragma unroll
        for (int r = 0; r < 4; r++) {
            u64t wp = wsd[(oc0 + r) * 64 + kk];
            acc[r][0] = ffma2(wp, x2[0], acc[r][0]);
            acc[r][1] = ffma2(wp, x2[1], acc[r][1]);
        }
    }

    int y  = py * 8 + (lane >> 2);
    int xg = px2 * 16 + (lane & 3) * 4;
    float* ob = out + (size_t)b * C * HW + (size_t)y * Wdim + xg;
    #pragma unroll
    for (int r = 0; r < 4; r++) {
        float o0, o1, o2v, o3;
        upk2(acc[r][0], o0, o1);
        upk2(acc[r][1], o2v, o3);
        *(float4*)(ob + (size_t)(oc0 + r) * HW) = make_float4(o0, o1, o2v, o3);
    }
}

// ---------------------------------------------------------------------------
extern "C" void kernel_launch(void* const* d_in, const int* in_sizes, int n_in,
                              void* d_out, int out_size) {
    const float* x           = (const float*)d_in[0];
    const float* qkv_w       = (const float*)d_in[1];
    const float* dw_w        = (const float*)d_in[2];
    const float* proj_w      = (const float*)d_in[3];
    const float* temperature = (const float*)d_in[4];
    float* out = (float*)d_out;

    cudaFuncSetAttribute(k_qkv,
                         cudaFuncAttributeMaxDynamicSharedMemorySize, 57344);
    cudaFuncSetAttribute(k_attn_proj,
                         cudaFuncAttributeMaxDynamicSharedMemorySize, 101376);

    k_qkv <<<dim3(B * 512, 2), 256, 57344>>>(x, qkv_w);
    k_dw  <<<B * C3, 256>>>(dw_w);
    k_attn_proj<<<B * 512, 512, 101376>>>(temperature, proj_w, out);
}

// round 15
// speedup vs baseline: 1.4935x; 1.0259x over previous
#include <cuda_runtime.h>
#include <cstdint>

#define B    8
#define C    64
#define C3   192
#define Hdim 256
#define Wdim 256
#define HW   65536

// Scratch (device globals: allocation-free per harness rules)
__device__ float g_qkv[(size_t)B * C3 * HW];  // after 1x1 qkv conv (std NCHW)
__device__ float g_p  [(size_t)B * C3 * HW];  // after depthwise, patch-blocked:
                                              // [b*C3+ch][patchIdx(1024)][64]

// ---------------------------------------------------------------------------
// Packed fp32x2 helpers (Blackwell base-arch packed math; exact fp32 lanes)
// ---------------------------------------------------------------------------
typedef unsigned long long u64t;

__device__ __forceinline__ u64t pk2(float lo, float hi) {
    u64t d;
    asm("mov.b64 %0, {%1, %2};" : "=l"(d) : "f"(lo), "f"(hi));
    return d;
}
__device__ __forceinline__ void upk2(u64t v, float& lo, float& hi) {
    asm("mov.b64 {%0, %1}, %2;" : "=f"(lo), "=f"(hi) : "l"(v));
}
__device__ __forceinline__ u64t ffma2(u64t a, u64t b, u64t c) {
    u64t d;
    asm("fma.rn.f32x2 %0, %1, %2, %3;" : "=l"(d) : "l"(a), "l"(b), "l"(c));
    return d;
}

// ---------------------------------------------------------------------------
// K1: 1x1 qkv GEMM (unchanged from R14). CTA = 128-px tile x 96 oc; 256 thr.
// ---------------------------------------------------------------------------
__global__ __launch_bounds__(256, 3) void k_qkv(const float* __restrict__ x,
                                                const float* __restrict__ w) {
    extern __shared__ float sm[];
    u64t*  wp2 = (u64t*)sm;          // [48 pair][64 ic] = {w[2p][ic], w[2p+1][ic]}
    float* xs  = sm + 6144;          // [64 ic][128 px]
    int b   = blockIdx.x >> 9;
    int px0 = (blockIdx.x & 511) << 7;
    int ocH = blockIdx.y * 96;
    int t   = threadIdx.x;

    #pragma unroll
    for (int k = 0; k < 12; k++) {
        int i  = t + k * 256;
        int pr = i >> 6, ic = i & 63;
        wp2[i] = pk2(w[(ocH + 2 * pr) * 64 + ic], w[(ocH + 2 * pr + 1) * 64 + ic]);
    }
    const float* xb = x + (size_t)b * C * HW + px0;
    #pragma unroll
    for (int k = 0; k < 8; k++) {
        int i  = t + k * 256;
        int ic = i >> 5, p4 = i & 31;
        *(float4*)(xs + ic * 128 + p4 * 4) =
            *(const float4*)(xb + (size_t)ic * HW + p4 * 4);
    }
    __syncthreads();

    int lane   = t & 31;
    int wpair0 = (t >> 5) * 6;

    u64t acc[6][4];
    #pragma unroll
    for (int r = 0; r < 6; r++)
        #pragma unroll
        for (int j = 0; j < 4; j++) acc[r][j] = 0ull;

    #pragma unroll 4
    for (int ic = 0; ic < 64; ic++) {
        float4 a = *(const float4*)(xs + ic * 128 + lane * 4);
        u64t xd[4] = {pk2(a.x, a.x), pk2(a.y, a.y), pk2(a.z, a.z), pk2(a.w, a.w)};
        #pragma unroll
        for (int r = 0; r < 6; r++) {
            u64t wp = wp2[(wpair0 + r) * 64 + ic];
            #pragma unroll
            for (int j = 0; j < 4; j++) acc[r][j] = ffma2(wp, xd[j], acc[r][j]);
        }
    }

    float* ob = g_qkv + (size_t)b * C3 * HW + px0 + lane * 4;
    #pragma unroll
    for (int r = 0; r < 6; r++) {
        int oc0 = ocH + 2 * (wpair0 + r);
        float e0, o0, e1, o1, e2, o2, e3, o3;
        upk2(acc[r][0], e0, o0); upk2(acc[r][1], e1, o1);
        upk2(acc[r][2], e2, o2); upk2(acc[r][3], e3, o3);
        *(float4*)(ob + (size_t)oc0 * HW)       = make_float4(e0, e1, e2, e3);
        *(float4*)(ob + (size_t)(oc0 + 1) * HW) = make_float4(o0, o1, o2, o3);
    }
}

// ---------------------------------------------------------------------------
// K2: 3x3 depthwise conv (unchanged from R14).
// ---------------------------------------------------------------------------
__global__ __launch_bounds__(256) void k_dw(const float* __restrict__ dw) {
    __shared__ float rows[4][258];
    int plane = blockIdx.x;
    int ch    = plane % C3;
    const float* ip = g_qkv + (size_t)plane * HW;
    float* op = g_p + (size_t)plane * HW;
    int t = threadIdx.x;

    float wreg[9];
    #pragma unroll
    for (int i = 0; i < 9; i++) wreg[i] = __ldg(dw + ch * 9 + i);

    if (t < 8) rows[t >> 1][(t & 1) ? 257 : 0] = 0.f;
    rows[0][t + 1] = 0.f;
    rows[1][t + 1] = ip[t];

    for (int y = 0; y < 256; y += 2) {
        int sA = (y + 2) & 3;
        int sB = (y + 3) & 3;
        __syncthreads();
        rows[sA][t + 1] = ip[(y + 1) * 256 + t];
        rows[sB][t + 1] = (y + 2 < 256) ? ip[(y + 2) * 256 + t] : 0.f;
        __syncthreads();

        const float* r0 = rows[y & 3];
        const float* r1 = rows[(y + 1) & 3];
        const float* r2 = rows[sA];
        const float* r3 = rows[sB];

        float a0 = wreg[0]*r0[t] + wreg[1]*r0[t+1] + wreg[2]*r0[t+2]
                 + wreg[3]*r1[t] + wreg[4]*r1[t+1] + wreg[5]*r1[t+2]
                 + wreg[6]*r2[t] + wreg[7]*r2[t+1] + wreg[8]*r2[t+2];
        float a1 = wreg[0]*r1[t] + wreg[1]*r1[t+1] + wreg[2]*r1[t+2]
                 + wreg[3]*r2[t] + wreg[4]*r2[t+1] + wreg[5]*r2[t+2]
                 + wreg[6]*r3[t] + wreg[7]*r3[t+1] + wreg[8]*r3[t+2];

        int gp0 = (y >> 3) * 32 + (t >> 3);
        int wi0 = (y & 7) * 8 + (t & 7);
        op[(size_t)gp0 * 64 + wi0] = a0;
        int gp1 = ((y + 1) >> 3) * 32 + (t >> 3);
        int wi1 = ((y + 1) & 7) * 8 + (t & 7);
        op[(size_t)gp1 * 64 + wi1] = a1;
    }
}

// ---------------------------------------------------------------------------
// K3 v2: fused patch-attention + 1x1 proj.
// - pd table: pd[ch][r][m] = {k[m], k[m-1]} built ONCE per patch at load
//   (shfl for the cross-half neighbor). Attn inner loop is pk2-free.
// - q pairs via ulonglong2 reinterpret (ascending pairs are memory order).
// - pd layout: r-stride 10 u64 (odd chunk count -> conflict-free LDS.128
//   within each fixed-ch lane octet), ch-stride 82 u64.
// - proj weights as oc-pairs (16KB); thread = 2 oc-pairs x 4 px.
// smem: wp2 16384 + qs 17408 + pd 41984 + att_s 32768 = 108544 B, 2 CTAs/SM.
// ---------------------------------------------------------------------------
__device__ __forceinline__ int att_sw(int g) { return g ^ ((g >> 3) & 3); }

#define AP_SMEM 108544

__global__ __launch_bounds__(512, 2) void k_attn_proj(
        const float* __restrict__ temperature,
        const float* __restrict__ pw,
        float* __restrict__ out) {
    extern __shared__ float sm[];
    u64t*  wp2   = (u64t*)sm;             // [32 ocpair][64 k]          16384 B
    float* qs    = sm + 4096;             // [64 ch][68] (stride 68)    17408 B
    u64t*  pd    = (u64t*)(sm + 8448);    // [64 ch][stride 82]: r*10+m 41984 B
    float* att_s = sm + 18944;            // [64 ch][128 px] swizzled   32768 B

    int t   = threadIdx.x;
    int bid = blockIdx.x;
    int b   = bid >> 9;
    int r9  = bid & 511;
    int py  = r9 >> 4;
    int px2 = r9 & 15;

    // proj weights as oc-pairs {w[2r][k], w[2r+1][k]}
    #pragma unroll
    for (int i = 0; i < 4; i++) {
        int idx = t + i * 512;            // 0..2047 = pair*64 + k
        int pr = idx >> 6, kk = idx & 63;
        wp2[idx] = pk2(pw[(2 * pr) * 64 + kk], pw[(2 * pr + 1) * 64 + kk]);
    }

    int ch = t >> 3, i = t & 7;
    float tmp = __ldg(temperature + ch);

    for (int p = 0; p < 2; p++) {
        int patch = py * 32 + px2 * 2 + p;
        __syncthreads();                  // protect q/pd reuse from prev iter

        // load q (ch 0..63) and k->pd (ch 64..127)
        for (int idx = t; idx < 1024; idx += 512) {
            int lch = idx >> 4, rem = idx & 15;
            int p1 = rem >> 1, hf = rem & 1;     // row, half
            const float* qsrc = g_p + ((size_t)(b * C3 + lch) * 1024 + patch) * 64
                              + p1 * 8 + hf * 4;
            *(float4*)(qs + lch * 68 + p1 * 8 + hf * 4) = *(const float4*)qsrc;

            float4 kv = *(const float4*)(qsrc + (size_t)64 * 1024 * 64);
            // neighbor below this half's first elem: partner(hf^1).w
            float kprev = __shfl_xor_sync(0xFFFFFFFFu, kv.w, 1);
            u64t* pr_ = pd + lch * 82 + p1 * 10 + hf * 4;
            ulonglong2 s0, s1;
            s0.x = pk2(kv.x, kprev);      // pd[m]   = {k[m],   k[m-1]}
            s0.y = pk2(kv.y, kv.x);
            s1.x = pk2(kv.z, kv.y);
            s1.y = pk2(kv.w, kv.z);
            *(ulonglong2*)pr_       = s0;
            *(ulonglong2*)(pr_ + 2) = s1;
        }
        __syncthreads();

        u64t o2[8];
        #pragma unroll
        for (int j = 0; j < 8; j++) o2[j] = 0ull;

        const u64t* qrow = (const u64t*)(qs + ch * 68);
        const u64t* pdch = pd + ch * 82;
        #pragma unroll
        for (int u = 0; u < 8; u++) {
            int r = (i - u) & 7;
            ulonglong2 qA = *(const ulonglong2*)(qrow + u * 4);
            ulonglong2 qB = *(const ulonglong2*)(qrow + u * 4 + 2);
            const u64t* pr_ = pdch + r * 10;
            ulonglong2 p01 = *(const ulonglong2*)(pr_);
            ulonglong2 p23 = *(const ulonglong2*)(pr_ + 2);
            ulonglong2 p45 = *(const ulonglong2*)(pr_ + 4);
            ulonglong2 p67 = *(const ulonglong2*)(pr_ + 6);
            u64t q2[4]  = {qA.x, qA.y, qB.x, qB.y};
            u64t pdr[8] = {p01.x, p01.y, p23.x, p23.y,
                           p45.x, p45.y, p67.x, p67.y};
            #pragma unroll
            for (int j = 0; j < 8; j++)
                #pragma unroll
                for (int a = 0; a < 4; a++)
                    o2[j] = ffma2(q2[a], pdr[(j - 2 * a) & 7], o2[j]);
        }
        float o[8];
        #pragma unroll
        for (int j = 0; j < 8; j++) {
            float lo, hi;
            upk2(o2[j], lo, hi);
            o[j] = lo + hi;
        }

        const float* vsrc = g_p + ((size_t)(b * C3 + 128 + ch) * 1024 + patch) * 64
                          + i * 8;
        float4 v0 = *(const float4*)vsrc;
        float4 v1 = *(const float4*)(vsrc + 4);
        int g0 = att_sw(i * 4 + p * 2 + 0);
        int g1 = att_sw(i * 4 + p * 2 + 1);
        *(float4*)(att_s + ch * 128 + g0 * 4) =
            make_float4(o[0]*tmp*v0.x, o[1]*tmp*v0.y, o[2]*tmp*v0.z, o[3]*tmp*v0.w);
        *(float4*)(att_s + ch * 128 + g1 * 4) =
            make_float4(o[4]*tmp*v1.x, o[5]*tmp*v1.y, o[6]*tmp*v1.z, o[7]*tmp*v1.w);
    }
    __syncthreads();

    // ---- proj: 64oc x 128px; thread = 2 oc-pairs x 4 px ----
    int lane = t & 31;
    int wpr0 = (t >> 5) * 2;              // first oc-pair (0..30)
    int gphys = att_sw(lane);

    u64t acc[2][4];
    #pragma unroll
    for (int r = 0; r < 2; r++)
        #pragma unroll
        for (int j = 0; j < 4; j++) acc[r][j] = 0ull;

    #pragma unroll 4
    for (int kk = 0; kk < 64; kk++) {
        float4 a = *(const float4*)(att_s + kk * 128 + gphys * 4);
        u64t ad[4] = {pk2(a.x, a.x), pk2(a.y, a.y), pk2(a.z, a.z), pk2(a.w, a.w)};
        #pragma unroll
        for (int r = 0; r < 2; r++) {
            u64t wp = wp2[(wpr0 + r) * 64 + kk];
            #pragma unroll
            for (int j = 0; j < 4; j++) acc[r][j] = ffma2(wp, ad[j], acc[r][j]);
        }
    }

    int y  = py * 8 + (lane >> 2);
    int xg = px2 * 16 + (lane & 3) * 4;
    float* ob = out + (size_t)b * C * HW + (size_t)y * Wdim + xg;
    #pragma unroll
    for (int r = 0; r < 2; r++) {
        int oc0 = 2 * (wpr0 + r);
        float e0, od0, e1, od1, e2, od2, e3, od3;
        upk2(acc[r][0], e0, od0); upk2(acc[r][1], e1, od1);
        upk2(acc[r][2], e2, od2); upk2(acc[r][3], e3, od3);
        *(float4*)(ob + (size_t)oc0 * HW)       = make_float4(e0, e1, e2, e3);
        *(float4*)(ob + (size_t)(oc0 + 1) * HW) = make_float4(od0, od1, od2, od3);
    }
}

// ---------------------------------------------------------------------------
extern "C" void kernel_launch(void* const* d_in, const int* in_sizes, int n_in,
                              void* d_out, int out_size) {
    const float* x           = (const float*)d_in[0];
    const float* qkv_w       = (const float*)d_in[1];
    const float* dw_w        = (const float*)d_in[2];
    const float* proj_w      = (const float*)d_in[3];
    const float* temperature = (const float*)d_in[4];
    float* out = (float*)d_out;

    cudaFuncSetAttribute(k_qkv,
                         cudaFuncAttributeMaxDynamicSharedMemorySize, 57344);
    cudaFuncSetAttribute(k_attn_proj,
                         cudaFuncAttributeMaxDynamicSharedMemorySize, AP_SMEM);

    k_qkv <<<dim3(B * 512, 2), 256, 57344>>>(x, qkv_w);
    k_dw  <<<B * C3, 256>>>(dw_w);
    k_attn_proj<<<B * 512, 512, AP_SMEM>>>(temperature, proj_w, out);
}

// round 16
// speedup vs baseline: 1.4989x; 1.0036x over previous
#include <cuda_runtime.h>
#include <cstdint>

#define B    8
#define C    64
#define C3   192
#define Hdim 256
#define Wdim 256
#define HW   65536

// Scratch (device globals: allocation-free per harness rules)
__device__ float g_qkv[(size_t)B * C3 * HW];  // after 1x1 qkv conv (std NCHW)
__device__ float g_p  [(size_t)B * C3 * HW];  // after depthwise, patch-blocked:
                                              // [b*C3+ch][patchIdx(1024)][64]

// ---------------------------------------------------------------------------
// Packed fp32x2 helpers (Blackwell base-arch packed math; exact fp32 lanes)
// ---------------------------------------------------------------------------
typedef unsigned long long u64t;

__device__ __forceinline__ u64t pk2(float lo, float hi) {
    u64t d;
    asm("mov.b64 %0, {%1, %2};" : "=l"(d) : "f"(lo), "f"(hi));
    return d;
}
__device__ __forceinline__ void upk2(u64t v, float& lo, float& hi) {
    asm("mov.b64 {%0, %1}, %2;" : "=f"(lo), "=f"(hi) : "l"(v));
}
__device__ __forceinline__ u64t ffma2(u64t a, u64t b, u64t c) {
    u64t d;
    asm("fma.rn.f32x2 %0, %1, %2, %3;" : "=l"(d) : "l"(a), "l"(b), "l"(c));
    return d;
}

// ---------------------------------------------------------------------------
// K1: 1x1 qkv GEMM. CTA = 128-px tile x 96 oc; 256 threads = 8 warps;
// warp = 6 oc-pairs (12 oc) in f32x2 lanes, lane = 4 px.
// Weight fetch: ONE LDS.128 broadcast per oc-pair per 2 ic ({w(ic),w(ic+1)}).
// Per warp per 2 ic: 2x LDS.128 x (8wf) + 6x LDS.128 bcast (6wf) -> 96 FMA.
// ---------------------------------------------------------------------------
__global__ __launch_bounds__(256, 3) void k_qkv(const float* __restrict__ x,
                                                const float* __restrict__ w) {
    extern __shared__ float sm[];
    u64t*  wp2 = (u64t*)sm;          // [48 pair][64 ic] = {w[2p][ic], w[2p+1][ic]}
    float* xs  = sm + 6144;          // [64 ic][128 px]
    int b   = blockIdx.x >> 9;
    int px0 = (blockIdx.x & 511) << 7;
    int ocH = blockIdx.y * 96;
    int t   = threadIdx.x;

    #pragma unroll
    for (int k = 0; k < 12; k++) {
        int i  = t + k * 256;
        int pr = i >> 6, ic = i & 63;
        wp2[i] = pk2(w[(ocH + 2 * pr) * 64 + ic], w[(ocH + 2 * pr + 1) * 64 + ic]);
    }
    const float* xb = x + (size_t)b * C * HW + px0;
    #pragma unroll
    for (int k = 0; k < 8; k++) {
        int i  = t + k * 256;
        int ic = i >> 5, p4 = i & 31;
        *(float4*)(xs + ic * 128 + p4 * 4) =
            *(const float4*)(xb + (size_t)ic * HW + p4 * 4);
    }
    __syncthreads();

    int lane   = t & 31;
    int wpair0 = (t >> 5) * 6;

    u64t acc[6][4];
    #pragma unroll
    for (int r = 0; r < 6; r++)
        #pragma unroll
        for (int j = 0; j < 4; j++) acc[r][j] = 0ull;

    #pragma unroll 4
    for (int ic0 = 0; ic0 < 64; ic0 += 2) {
        float4 a0 = *(const float4*)(xs + ic0 * 128 + lane * 4);
        float4 a1 = *(const float4*)(xs + (ic0 + 1) * 128 + lane * 4);
        u64t xd0[4] = {pk2(a0.x, a0.x), pk2(a0.y, a0.y),
                       pk2(a0.z, a0.z), pk2(a0.w, a0.w)};
        u64t xd1[4] = {pk2(a1.x, a1.x), pk2(a1.y, a1.y),
                       pk2(a1.z, a1.z), pk2(a1.w, a1.w)};
        #pragma unroll
        for (int r = 0; r < 6; r++) {
            ulonglong2 wq = *(const ulonglong2*)(wp2 + (wpair0 + r) * 64 + ic0);
            #pragma unroll
            for (int j = 0; j < 4; j++) acc[r][j] = ffma2(wq.x, xd0[j], acc[r][j]);
            #pragma unroll
            for (int j = 0; j < 4; j++) acc[r][j] = ffma2(wq.y, xd1[j], acc[r][j]);
        }
    }

    float* ob = g_qkv + (size_t)b * C3 * HW + px0 + lane * 4;
    #pragma unroll
    for (int r = 0; r < 6; r++) {
        int oc0 = ocH + 2 * (wpair0 + r);
        float e0, o0, e1, o1, e2, o2, e3, o3;
        upk2(acc[r][0], e0, o0); upk2(acc[r][1], e1, o1);
        upk2(acc[r][2], e2, o2); upk2(acc[r][3], e3, o3);
        *(float4*)(ob + (size_t)oc0 * HW)       = make_float4(e0, e1, e2, e3);
        *(float4*)(ob + (size_t)(oc0 + 1) * HW) = make_float4(o0, o1, o2, o3);
    }
}

// ---------------------------------------------------------------------------
// K2: 3x3 depthwise conv (unchanged).
// ---------------------------------------------------------------------------
__global__ __launch_bounds__(256) void k_dw(const float* __restrict__ dw) {
    __shared__ float rows[4][258];
    int plane = blockIdx.x;
    int ch    = plane % C3;
    const float* ip = g_qkv + (size_t)plane * HW;
    float* op = g_p + (size_t)plane * HW;
    int t = threadIdx.x;

    float wreg[9];
    #pragma unroll
    for (int i = 0; i < 9; i++) wreg[i] = __ldg(dw + ch * 9 + i);

    if (t < 8) rows[t >> 1][(t & 1) ? 257 : 0] = 0.f;
    rows[0][t + 1] = 0.f;
    rows[1][t + 1] = ip[t];

    for (int y = 0; y < 256; y += 2) {
        int sA = (y + 2) & 3;
        int sB = (y + 3) & 3;
        __syncthreads();
        rows[sA][t + 1] = ip[(y + 1) * 256 + t];
        rows[sB][t + 1] = (y + 2 < 256) ? ip[(y + 2) * 256 + t] : 0.f;
        __syncthreads();

        const float* r0 = rows[y & 3];
        const float* r1 = rows[(y + 1) & 3];
        const float* r2 = rows[sA];
        const float* r3 = rows[sB];

        float a0 = wreg[0]*r0[t] + wreg[1]*r0[t+1] + wreg[2]*r0[t+2]
                 + wreg[3]*r1[t] + wreg[4]*r1[t+1] + wreg[5]*r1[t+2]
                 + wreg[6]*r2[t] + wreg[7]*r2[t+1] + wreg[8]*r2[t+2];
        float a1 = wreg[0]*r1[t] + wreg[1]*r1[t+1] + wreg[2]*r1[t+2]
                 + wreg[3]*r2[t] + wreg[4]*r2[t+1] + wreg[5]*r2[t+2]
                 + wreg[6]*r3[t] + wreg[7]*r3[t+1] + wreg[8]*r3[t+2];

        int gp0 = (y >> 3) * 32 + (t >> 3);
        int wi0 = (y & 7) * 8 + (t & 7);
        op[(size_t)gp0 * 64 + wi0] = a0;
        int gp1 = ((y + 1) >> 3) * 32 + (t >> 3);
        int wi1 = ((y + 1) & 7) * 8 + (t & 7);
        op[(size_t)gp1 * 64 + wi1] = a1;
    }
}

// ---------------------------------------------------------------------------
// K3: fused patch-attention + 1x1 proj (R15 structure; proj loop now fetches
// w-pairs 2 kk at a time via LDS.128 broadcast).
// ---------------------------------------------------------------------------
__device__ __forceinline__ int att_sw(int g) { return g ^ ((g >> 3) & 3); }

#define AP_SMEM 108544

__global__ __launch_bounds__(512, 2) void k_attn_proj(
        const float* __restrict__ temperature,
        const float* __restrict__ pw,
        float* __restrict__ out) {
    extern __shared__ float sm[];
    u64t*  wp2   = (u64t*)sm;             // [32 ocpair][64 k]          16384 B
    float* qs    = sm + 4096;             // [64 ch][68] (stride 68)    17408 B
    u64t*  pd    = (u64t*)(sm + 8448);    // [64 ch][stride 82]: r*10+m 41984 B
    float* att_s = sm + 18944;            // [64 ch][128 px] swizzled   32768 B

    int t   = threadIdx.x;
    int bid = blockIdx.x;
    int b   = bid >> 9;
    int r9  = bid & 511;
    int py  = r9 >> 4;
    int px2 = r9 & 15;

    // proj weights as oc-pairs {w[2r][k], w[2r+1][k]}
    #pragma unroll
    for (int i = 0; i < 4; i++) {
        int idx = t + i * 512;            // 0..2047 = pair*64 + k
        int pr = idx >> 6, kk = idx & 63;
        wp2[idx] = pk2(pw[(2 * pr) * 64 + kk], pw[(2 * pr + 1) * 64 + kk]);
    }

    int ch = t >> 3, i = t & 7;
    float tmp = __ldg(temperature + ch);

    for (int p = 0; p < 2; p++) {
        int patch = py * 32 + px2 * 2 + p;
        __syncthreads();                  // protect q/pd reuse from prev iter

        // load q (ch 0..63) and k->pd (ch 64..127)
        for (int idx = t; idx < 1024; idx += 512) {
            int lch = idx >> 4, rem = idx & 15;
            int p1 = rem >> 1, hf = rem & 1;     // row, half
            const float* qsrc = g_p + ((size_t)(b * C3 + lch) * 1024 + patch) * 64
                              + p1 * 8 + hf * 4;
            *(float4*)(qs + lch * 68 + p1 * 8 + hf * 4) = *(const float4*)qsrc;

            float4 kv = *(const float4*)(qsrc + (size_t)64 * 1024 * 64);
            // neighbor below this half's first elem: partner(hf^1).w
            float kprev = __shfl_xor_sync(0xFFFFFFFFu, kv.w, 1);
            u64t* pr_ = pd + lch * 82 + p1 * 10 + hf * 4;
            ulonglong2 s0, s1;
            s0.x = pk2(kv.x, kprev);      // pd[m]   = {k[m],   k[m-1]}
            s0.y = pk2(kv.y, kv.x);
            s1.x = pk2(kv.z, kv.y);
            s1.y = pk2(kv.w, kv.z);
            *(ulonglong2*)pr_       = s0;
            *(ulonglong2*)(pr_ + 2) = s1;
        }
        __syncthreads();

        u64t o2[8];
        #pragma unroll
        for (int j = 0; j < 8; j++) o2[j] = 0ull;

        const u64t* qrow = (const u64t*)(qs + ch * 68);
        const u64t* pdch = pd + ch * 82;
        #pragma unroll
        for (int u = 0; u < 8; u++) {
            int r = (i - u) & 7;
            ulonglong2 qA = *(const ulonglong2*)(qrow + u * 4);
            ulonglong2 qB = *(const ulonglong2*)(qrow + u * 4 + 2);
            const u64t* pr_ = pdch + r * 10;
            ulonglong2 p01 = *(const ulonglong2*)(pr_);
            ulonglong2 p23 = *(const ulonglong2*)(pr_ + 2);
            ulonglong2 p45 = *(const ulonglong2*)(pr_ + 4);
            ulonglong2 p67 = *(const ulonglong2*)(pr_ + 6);
            u64t q2[4]  = {qA.x, qA.y, qB.x, qB.y};
            u64t pdr[8] = {p01.x, p01.y, p23.x, p23.y,
                           p45.x, p45.y, p67.x, p67.y};
            #pragma unroll
            for (int j = 0; j < 8; j++)
                #pragma unroll
                for (int a = 0; a < 4; a++)
                    o2[j] = ffma2(q2[a], pdr[(j - 2 * a) & 7], o2[j]);
        }
        float o[8];
        #pragma unroll
        for (int j = 0; j < 8; j++) {
            float lo, hi;
            upk2(o2[j], lo, hi);
            o[j] = lo + hi;
        }

        const float* vsrc = g_p + ((size_t)(b * C3 + 128 + ch) * 1024 + patch) * 64
                          + i * 8;
        float4 v0 = *(const float4*)vsrc;
        float4 v1 = *(const float4*)(vsrc + 4);
        int g0 = att_sw(i * 4 + p * 2 + 0);
        int g1 = att_sw(i * 4 + p * 2 + 1);
        *(float4*)(att_s + ch * 128 + g0 * 4) =
            make_float4(o[0]*tmp*v0.x, o[1]*tmp*v0.y, o[2]*tmp*v0.z, o[3]*tmp*v0.w);
        *(float4*)(att_s + ch * 128 + g1 * 4) =
            make_float4(o[4]*tmp*v1.x, o[5]*tmp*v1.y, o[6]*tmp*v1.z, o[7]*tmp*v1.w);
    }
    __syncthreads();

    // ---- proj: 64oc x 128px; thread = 2 oc-pairs x 4 px, 2 kk per step ----
    int lane = t & 31;
    int wpr0 = (t >> 5) * 2;              // first oc-pair (0..30)
    int gphys = att_sw(lane);

    u64t acc[2][4];
    #pragma unroll
    for (int r = 0; r < 2; r++)
        #pragma unroll
        for (int j = 0; j < 4; j++) acc[r][j] = 0ull;

    #pragma unroll 4
    for (int kk = 0; kk < 64; kk += 2) {
        float4 a = *(const float4*)(att_s + kk * 128 + gphys * 4);
        float4 c = *(const float4*)(att_s + (kk + 1) * 128 + gphys * 4);
        u64t ad[4] = {pk2(a.x, a.x), pk2(a.y, a.y), pk2(a.z, a.z), pk2(a.w, a.w)};
        u64t cd[4] = {pk2(c.x, c.x), pk2(c.y, c.y), pk2(c.z, c.z), pk2(c.w, c.w)};
        #pragma unroll
        for (int r = 0; r < 2; r++) {
            ulonglong2 wq = *(const ulonglong2*)(wp2 + (wpr0 + r) * 64 + kk);
            #pragma unroll
            for (int j = 0; j < 4; j++) acc[r][j] = ffma2(wq.x, ad[j], acc[r][j]);
            #pragma unroll
            for (int j = 0; j < 4; j++) acc[r][j] = ffma2(wq.y, cd[j], acc[r][j]);
        }
    }

    int y  = py * 8 + (lane >> 2);
    int xg = px2 * 16 + (lane & 3) * 4;
    float* ob = out + (size_t)b * C * HW + (size_t)y * Wdim + xg;
    #pragma unroll
    for (int r = 0; r < 2; r++) {
        int oc0 = 2 * (wpr0 + r);
        float e0, od0, e1, od1, e2, od2, e3, od3;
        upk2(acc[r][0], e0, od0); upk2(acc[r][1], e1, od1);
        upk2(acc[r][2], e2, od2); upk2(acc[r][3], e3, od3);
        *(float4*)(ob + (size_t)oc0 * HW)       = make_float4(e0, e1, e2, e3);
        *(float4*)(ob + (size_t)(oc0 + 1) * HW) = make_float4(od0, od1, od2, od3);
    }
}

// ---------------------------------------------------------------------------
extern "C" void kernel_launch(void* const* d_in, const int* in_sizes, int n_in,
                              void* d_out, int out_size) {
    const float* x           = (const float*)d_in[0];
    const float* qkv_w       = (const float*)d_in[1];
    const float* dw_w        = (const float*)d_in[2];
    const float* proj_w      = (const float*)d_in[3];
    const float* temperature = (const float*)d_in[4];
    float* out = (float*)d_out;

    cudaFuncSetAttribute(k_qkv,
                         cudaFuncAttributeMaxDynamicSharedMemorySize, 57344);
    cudaFuncSetAttribute(k_attn_proj,
                         cudaFuncAttributeMaxDynamicSharedMemorySize, AP_SMEM);

    k_qkv <<<dim3(B * 512, 2), 256, 57344>>>(x, qkv_w);
    k_dw  <<<B * C3, 256>>>(dw_w);
    k_attn_proj<<<B * 512, 512, AP_SMEM>>>(temperature, proj_w, out);
}

// round 17
// speedup vs baseline: 1.6151x; 1.0776x over previous
#include <cuda_runtime.h>
#include <cstdint>

#define B    8
#define C    64
#define C3   192
#define Hdim 256
#define Wdim 256
#define HW   65536

// Scratch (device globals: allocation-free per harness rules)
__device__ float g_qkv[(size_t)B * C3 * HW];  // after 1x1 qkv conv (std NCHW)
__device__ float g_p  [(size_t)B * C3 * HW];  // after depthwise, patch-blocked:
                                              // [b*C3+ch][patchIdx(1024)][64]

// ---------------------------------------------------------------------------
// Packed fp32x2 helpers (Blackwell base-arch packed math; exact fp32 lanes)
// ---------------------------------------------------------------------------
typedef unsigned long long u64t;

__device__ __forceinline__ u64t pk2(float lo, float hi) {
    u64t d;
    asm("mov.b64 %0, {%1, %2};" : "=l"(d) : "f"(lo), "f"(hi));
    return d;
}
__device__ __forceinline__ void upk2(u64t v, float& lo, float& hi) {
    asm("mov.b64 {%0, %1}, %2;" : "=f"(lo), "=f"(hi) : "l"(v));
}
__device__ __forceinline__ u64t ffma2(u64t a, u64t b, u64t c) {
    u64t d;
    asm("fma.rn.f32x2 %0, %1, %2, %3;" : "=l"(d) : "l"(a), "l"(b), "l"(c));
    return d;
}

// ---------------------------------------------------------------------------
// K1: 1x1 qkv GEMM (unchanged from R16).
// ---------------------------------------------------------------------------
__global__ __launch_bounds__(256, 3) void k_qkv(const float* __restrict__ x,
                                                const float* __restrict__ w) {
    extern __shared__ float sm[];
    u64t*  wp2 = (u64t*)sm;          // [48 pair][64 ic]
    float* xs  = sm + 6144;          // [64 ic][128 px]
    int b   = blockIdx.x >> 9;
    int px0 = (blockIdx.x & 511) << 7;
    int ocH = blockIdx.y * 96;
    int t   = threadIdx.x;

    #pragma unroll
    for (int k = 0; k < 12; k++) {
        int i  = t + k * 256;
        int pr = i >> 6, ic = i & 63;
        wp2[i] = pk2(w[(ocH + 2 * pr) * 64 + ic], w[(ocH + 2 * pr + 1) * 64 + ic]);
    }
    const float* xb = x + (size_t)b * C * HW + px0;
    #pragma unroll
    for (int k = 0; k < 8; k++) {
        int i  = t + k * 256;
        int ic = i >> 5, p4 = i & 31;
        *(float4*)(xs + ic * 128 + p4 * 4) =
            *(const float4*)(xb + (size_t)ic * HW + p4 * 4);
    }
    __syncthreads();

    int lane   = t & 31;
    int wpair0 = (t >> 5) * 6;

    u64t acc[6][4];
    #pragma unroll
    for (int r = 0; r < 6; r++)
        #pragma unroll
        for (int j = 0; j < 4; j++) acc[r][j] = 0ull;

    #pragma unroll 4
    for (int ic0 = 0; ic0 < 64; ic0 += 2) {
        float4 a0 = *(const float4*)(xs + ic0 * 128 + lane * 4);
        float4 a1 = *(const float4*)(xs + (ic0 + 1) * 128 + lane * 4);
        u64t xd0[4] = {pk2(a0.x, a0.x), pk2(a0.y, a0.y),
                       pk2(a0.z, a0.z), pk2(a0.w, a0.w)};
        u64t xd1[4] = {pk2(a1.x, a1.x), pk2(a1.y, a1.y),
                       pk2(a1.z, a1.z), pk2(a1.w, a1.w)};
        #pragma unroll
        for (int r = 0; r < 6; r++) {
            ulonglong2 wq = *(const ulonglong2*)(wp2 + (wpair0 + r) * 64 + ic0);
            #pragma unroll
            for (int j = 0; j < 4; j++) acc[r][j] = ffma2(wq.x, xd0[j], acc[r][j]);
            #pragma unroll
            for (int j = 0; j < 4; j++) acc[r][j] = ffma2(wq.y, xd1[j], acc[r][j]);
        }
    }

    float* ob = g_qkv + (size_t)b * C3 * HW + px0 + lane * 4;
    #pragma unroll
    for (int r = 0; r < 6; r++) {
        int oc0 = ocH + 2 * (wpair0 + r);
        float e0, o0, e1, o1, e2, o2, e3, o3;
        upk2(acc[r][0], e0, o0); upk2(acc[r][1], e1, o1);
        upk2(acc[r][2], e2, o2); upk2(acc[r][3], e3, o3);
        *(float4*)(ob + (size_t)oc0 * HW)       = make_float4(e0, e1, e2, e3);
        *(float4*)(ob + (size_t)(oc0 + 1) * HW) = make_float4(o0, o1, o2, o3);
    }
}

// ---------------------------------------------------------------------------
// K2 v3: 3x3 depthwise conv, 8-row groups with smem output staging.
// Block = one (b,ch) plane, 256 thr = one full column each.
// Per group: load 10 halo rows (coalesced), compute 8 outputs/thread from
// register-hoisted columns, stage to obuf, then store patch-ordered as
// fully-contiguous 1KB warp stores (4 sectors/instr, was 8).
// ---------------------------------------------------------------------------
__global__ __launch_bounds__(256) void k_dw(const float* __restrict__ dw) {
    __shared__ float sx[10][258];
    __shared__ float obuf[8][260];
    int plane = blockIdx.x;
    int ch    = plane % C3;
    const float* ip = g_qkv + (size_t)plane * HW;
    float* op = g_p + (size_t)plane * HW;
    int t = threadIdx.x;

    float wreg[9];
    #pragma unroll
    for (int i = 0; i < 9; i++) wreg[i] = __ldg(dw + ch * 9 + i);

    // halo columns always zero (10 rows x 2 edges)
    if (t < 20) sx[t >> 1][(t & 1) ? 257 : 0] = 0.f;

    for (int g = 0; g < 32; g++) {
        int y0 = g * 8;
        __syncthreads();                 // prev iter's sx/obuf reads done
        #pragma unroll
        for (int rr = 0; rr < 10; rr++) {
            int y = y0 - 1 + rr;
            sx[rr][t + 1] = ((unsigned)y < 256u) ? ip[y * 256 + t] : 0.f;
        }
        __syncthreads();

        // hoist 3 columns x 10 rows into registers
        float a[10], bb[10], cc[10];
        #pragma unroll
        for (int rr = 0; rr < 10; rr++) {
            a[rr]  = sx[rr][t];
            bb[rr] = sx[rr][t + 1];
            cc[rr] = sx[rr][t + 2];
        }
        #pragma unroll
        for (int yy = 0; yy < 8; yy++) {
            float acc = wreg[0]*a[yy]   + wreg[1]*bb[yy]   + wreg[2]*cc[yy]
                      + wreg[3]*a[yy+1] + wreg[4]*bb[yy+1] + wreg[5]*cc[yy+1]
                      + wreg[6]*a[yy+2] + wreg[7]*bb[yy+2] + wreg[8]*cc[yy+2];
            obuf[yy][t] = acc;
        }
        __syncthreads();

        // patch-ordered store: thread t -> flat [g*2048 + t*8 .. +7]
        // flat f = patch*64 + row*8 + col ; patch = t>>3, row = t&7, col = k
        const float* src = &obuf[t & 7][(t >> 3) * 8];
        float4 u0 = *(const float4*)src;
        float4 u1 = *(const float4*)(src + 4);
        float* dst = op + g * 2048 + t * 8;
        *(float4*)dst       = u0;
        *(float4*)(dst + 4) = u1;
    }
}

// ---------------------------------------------------------------------------
// K3: fused patch-attention + 1x1 proj (unchanged from R16).
// ---------------------------------------------------------------------------
__device__ __forceinline__ int att_sw(int g) { return g ^ ((g >> 3) & 3); }

#define AP_SMEM 108544

__global__ __launch_bounds__(512, 2) void k_attn_proj(
        const float* __restrict__ temperature,
        const float* __restrict__ pw,
        float* __restrict__ out) {
    extern __shared__ float sm[];
    u64t*  wp2   = (u64t*)sm;             // [32 ocpair][64 k]          16384 B
    float* qs    = sm + 4096;             // [64 ch][68]                17408 B
    u64t*  pd    = (u64t*)(sm + 8448);    // [64 ch][stride 82]         41984 B
    float* att_s = sm + 18944;            // [64 ch][128 px] swizzled   32768 B

    int t   = threadIdx.x;
    int bid = blockIdx.x;
    int b   = bid >> 9;
    int r9  = bid & 511;
    int py  = r9 >> 4;
    int px2 = r9 & 15;

    #pragma unroll
    for (int i = 0; i < 4; i++) {
        int idx = t + i * 512;
        int pr = idx >> 6, kk = idx & 63;
        wp2[idx] = pk2(pw[(2 * pr) * 64 + kk], pw[(2 * pr + 1) * 64 + kk]);
    }

    int ch = t >> 3, i = t & 7;
    float tmp = __ldg(temperature + ch);

    for (int p = 0; p < 2; p++) {
        int patch = py * 32 + px2 * 2 + p;
        __syncthreads();

        for (int idx = t; idx < 1024; idx += 512) {
            int lch = idx >> 4, rem = idx & 15;
            int p1 = rem >> 1, hf = rem & 1;
            const float* qsrc = g_p + ((size_t)(b * C3 + lch) * 1024 + patch) * 64
                              + p1 * 8 + hf * 4;
            *(float4*)(qs + lch * 68 + p1 * 8 + hf * 4) = *(const float4*)qsrc;

            float4 kv = *(const float4*)(qsrc + (size_t)64 * 1024 * 64);
            float kprev = __shfl_xor_sync(0xFFFFFFFFu, kv.w, 1);
            u64t* pr_ = pd + lch * 82 + p1 * 10 + hf * 4;
            ulonglong2 s0, s1;
            s0.x = pk2(kv.x, kprev);
            s0.y = pk2(kv.y, kv.x);
            s1.x = pk2(kv.z, kv.y);
            s1.y = pk2(kv.w, kv.z);
            *(ulonglong2*)pr_       = s0;
            *(ulonglong2*)(pr_ + 2) = s1;
        }
        __syncthreads();

        u64t o2[8];
        #pragma unroll
        for (int j = 0; j < 8; j++) o2[j] = 0ull;

        const u64t* qrow = (const u64t*)(qs + ch * 68);
        const u64t* pdch = pd + ch * 82;
        #pragma unroll
        for (int u = 0; u < 8; u++) {
            int r = (i - u) & 7;
            ulonglong2 qA = *(const ulonglong2*)(qrow + u * 4);
            ulonglong2 qB = *(const ulonglong2*)(qrow + u * 4 + 2);
            const u64t* pr_ = pdch + r * 10;
            ulonglong2 p01 = *(const ulonglong2*)(pr_);
            ulonglong2 p23 = *(const ulonglong2*)(pr_ + 2);
            ulonglong2 p45 = *(const ulonglong2*)(pr_ + 4);
            ulonglong2 p67 = *(const ulonglong2*)(pr_ + 6);
            u64t q2[4]  = {qA.x, qA.y, qB.x, qB.y};
            u64t pdr[8] = {p01.x, p01.y, p23.x, p23.y,
                           p45.x, p45.y, p67.x, p67.y};
            #pragma unroll
            for (int j = 0; j < 8; j++)
                #pragma unroll
                for (int a = 0; a < 4; a++)
                    o2[j] = ffma2(q2[a], pdr[(j - 2 * a) & 7], o2[j]);
        }
        float o[8];
        #pragma unroll
        for (int j = 0; j < 8; j++) {
            float lo, hi;
            upk2(o2[j], lo, hi);
            o[j] = lo + hi;
        }

        const float* vsrc = g_p + ((size_t)(b * C3 + 128 + ch) * 1024 + patch) * 64
                          + i * 8;
        float4 v0 = *(const float4*)vsrc;
        float4 v1 = *(const float4*)(vsrc + 4);
        int g0 = att_sw(i * 4 + p * 2 + 0);
        int g1 = att_sw(i * 4 + p * 2 + 1);
        *(float4*)(att_s + ch * 128 + g0 * 4) =
            make_float4(o[0]*tmp*v0.x, o[1]*tmp*v0.y, o[2]*tmp*v0.z, o[3]*tmp*v0.w);
        *(float4*)(att_s + ch * 128 + g1 * 4) =
            make_float4(o[4]*tmp*v1.x, o[5]*tmp*v1.y, o[6]*tmp*v1.z, o[7]*tmp*v1.w);
    }
    __syncthreads();

    int lane = t & 31;
    int wpr0 = (t >> 5) * 2;
    int gphys = att_sw(lane);

    u64t acc[2][4];
    #pragma unroll
    for (int r = 0; r < 2; r++)
        #pragma unroll
        for (int j = 0; j < 4; j++) acc[r][j] = 0ull;

    #pragma unroll 4
    for (int kk = 0; kk < 64; kk += 2) {
        float4 a = *(const float4*)(att_s + kk * 128 + gphys * 4);
        float4 c = *(const float4*)(att_s + (kk + 1) * 128 + gphys * 4);
        u64t ad[4] = {pk2(a.x, a.x), pk2(a.y, a.y), pk2(a.z, a.z), pk2(a.w, a.w)};
        u64t cd[4] = {pk2(c.x, c.x), pk2(c.y, c.y), pk2(c.z, c.z), pk2(c.w, c.w)};
        #pragma unroll
        for (int r = 0; r < 2; r++) {
            ulonglong2 wq = *(const ulonglong2*)(wp2 + (wpr0 + r) * 64 + kk);
            #pragma unroll
            for (int j = 0; j < 4; j++) acc[r][j] = ffma2(wq.x, ad[j], acc[r][j]);
            #pragma unroll
            for (int j = 0; j < 4; j++) acc[r][j] = ffma2(wq.y, cd[j], acc[r][j]);
        }
    }

    int y  = py * 8 + (lane >> 2);
    int xg = px2 * 16 + (lane & 3) * 4;
    float* ob = out + (size_t)b * C * HW + (size_t)y * Wdim + xg;
    #pragma unroll
    for (int r = 0; r < 2; r++) {
        int oc0 = 2 * (wpr0 + r);
        float e0, od0, e1, od1, e2, od2, e3, od3;
        upk2(acc[r][0], e0, od0); upk2(acc[r][1], e1, od1);
        upk2(acc[r][2], e2, od2); upk2(acc[r][3], e3, od3);
        *(float4*)(ob + (size_t)oc0 * HW)       = make_float4(e0, e1, e2, e3);
        *(float4*)(ob + (size_t)(oc0 + 1) * HW) = make_float4(od0, od1, od2, od3);
    }
}

// ---------------------------------------------------------------------------
extern "C" void kernel_launch(void* const* d_in, const int* in_sizes, int n_in,
                              void* d_out, int out_size) {
    const float* x           = (const float*)d_in[0];
    const float* qkv_w       = (const float*)d_in[1];
    const float* dw_w        = (const float*)d_in[2];
    const float* proj_w      = (const float*)d_in[3];
    const float* temperature = (const float*)d_in[4];
    float* out = (float*)d_out;

    cudaFuncSetAttribute(k_qkv,
                         cudaFuncAttributeMaxDynamicSharedMemorySize, 57344);
    cudaFuncSetAttribute(k_attn_proj,
                         cudaFuncAttributeMaxDynamicSharedMemorySize, AP_SMEM);

    k_qkv <<<dim3(B * 512, 2), 256, 57344>>>(x, qkv_w);
    k_dw  <<<B * C3, 256>>>(dw_w);
    k_attn_proj<<<B * 512, 512, AP_SMEM>>>(temperature, proj_w, out);
}